// round 13
// baseline (speedup 1.0000x reference)
#include <cuda_runtime.h>
#include <cuda_bf16.h>
#include <math.h>
#include <cstdint>

#define NN 100000
#define EE 600000
#define DD 128
#define LL 5
#define BN_EPS 1e-5f
#define COMBO 7392
#define NCHUNK ((NN + 1023) / 1024)

// ---------------- device scratch ----------------
__device__ float  g_h[(size_t)NN * DD];                 // raw (pre-BN) layer output
__device__ __nv_bfloat16 g_agg_h[(size_t)NN * DD];
__device__ __nv_bfloat16 g_agg_l[(size_t)NN * DD];
__device__ __nv_bfloat16 g_hid_h[(size_t)NN * 2 * DD];
__device__ __nv_bfloat16 g_hid_l[(size_t)NN * 2 * DD];
__device__ __nv_bfloat16 g_w1h[DD * 2 * DD];
__device__ __nv_bfloat16 g_w1l[DD * 2 * DD];
__device__ __nv_bfloat16 g_w2h[2 * DD * DD];
__device__ __nv_bfloat16 g_w2l[2 * DD * DD];
__device__ float  g_combo[(size_t)COMBO * DD];
__device__ int    g_offs[NN + 1];
__device__ int    g_cursor[NN];
__device__ int    g_chunksums[NCHUNK];
__device__ int2   g_edge_data[EE];
__device__ double g_sum[DD];
__device__ double g_sumsq[DD];
__device__ float  g_scale[DD];
__device__ float  g_shift[DD];

static __device__ __forceinline__ float4 ld4(const float* p) {
    return *reinterpret_cast<const float4*>(p);
}
static __device__ __forceinline__ void add4(float4& a, const float4 b) {
    a.x += b.x; a.y += b.y; a.z += b.z; a.w += b.w;
}

// ================= MMA helpers =================
static __device__ __forceinline__ uint32_t smem_u32(const void* p) {
    uint32_t a;
    asm("{ .reg .u64 t; cvta.to.shared.u64 t, %1; cvt.u32.u64 %0, t; }" : "=r"(a) : "l"(p));
    return a;
}
static __device__ __forceinline__ void ldm_x4(uint32_t* r, uint32_t addr) {
    asm volatile("ldmatrix.sync.aligned.m8n8.x4.shared.b16 {%0,%1,%2,%3}, [%4];"
        : "=r"(r[0]), "=r"(r[1]), "=r"(r[2]), "=r"(r[3]) : "r"(addr));
}
static __device__ __forceinline__ void ldm_x4_t(uint32_t* r, uint32_t addr) {
    asm volatile("ldmatrix.sync.aligned.m8n8.x4.trans.shared.b16 {%0,%1,%2,%3}, [%4];"
        : "=r"(r[0]), "=r"(r[1]), "=r"(r[2]), "=r"(r[3]) : "r"(addr));
}
static __device__ __forceinline__ void mma_bf16(float* d, const uint32_t* a, const uint32_t* b) {
    asm volatile(
        "mma.sync.aligned.m16n8k16.row.col.f32.bf16.bf16.f32 "
        "{%0,%1,%2,%3}, {%4,%5,%6,%7}, {%8,%9}, {%0,%1,%2,%3};"
        : "+f"(d[0]), "+f"(d[1]), "+f"(d[2]), "+f"(d[3])
        : "r"(a[0]), "r"(a[1]), "r"(a[2]), "r"(a[3]), "r"(b[0]), "r"(b[1]));
}
static __device__ __forceinline__ void cp16(uint32_t dst, const void* src, int sz) {
    asm volatile("cp.async.cg.shared.global [%0], [%1], 16, %2;"
        :: "r"(dst), "l"(src), "r"(sz) : "memory");
}
static __device__ __forceinline__ void cp_commit() {
    asm volatile("cp.async.commit_group;" ::: "memory");
}
template <int Nk>
static __device__ __forceinline__ void cp_wait() {
    asm volatile("cp.async.wait_group %0;" :: "n"(Nk) : "memory");
}

// smem stage layout (bytes): A rows 80B stride, B rows 272B stride. 3 stages.
#define OFF_AH_ 0
#define OFF_AL_ 10240
#define OFF_BH_ 20480
#define OFF_BL_ 29184
#define GS_STAGE 37888
#define GEMM_SMEM (3 * GS_STAGE)

static __device__ __forceinline__ uint32_t pack_hi(float v0, float v1) {
    unsigned short h0 = __bfloat16_as_ushort(__float2bfloat16(v0));
    unsigned short h1 = __bfloat16_as_ushort(__float2bfloat16(v1));
    return (uint32_t)h0 | ((uint32_t)h1 << 16);
}
static __device__ __forceinline__ uint32_t pack_lo(float v0, float v1) {
    float f0 = __bfloat162float(__float2bfloat16(v0));
    float f1 = __bfloat162float(__float2bfloat16(v1));
    unsigned short l0 = __bfloat16_as_ushort(__float2bfloat16(v0 - f0));
    unsigned short l1 = __bfloat16_as_ushort(__float2bfloat16(v1 - f1));
    return (uint32_t)l0 | ((uint32_t)l1 << 16);
}

// MODE 0: relu, write bf16 hi/lo (Oh/Ol). MODE 1: no relu, write fp32 Of + column stats.
template <int N, int K, int MODE>
__global__ __launch_bounds__(256, 2) void hsplit_gemm(
    const __nv_bfloat16* __restrict__ Ah, const __nv_bfloat16* __restrict__ Al,
    const __nv_bfloat16* __restrict__ Bh, const __nv_bfloat16* __restrict__ Bl,
    const float* __restrict__ bias,
    __nv_bfloat16* __restrict__ Oh, __nv_bfloat16* __restrict__ Ol,
    float* __restrict__ Of, int M)
{
    extern __shared__ char smem[];
    const uint32_t sb = smem_u32(smem);
    const int tid = threadIdx.x;
    const int lane = tid & 31;
    const int w = tid >> 5;
    const int wm = w & 3;
    const int wn = w >> 2;
    const int bm = blockIdx.y * 128;
    const int bn = blockIdx.x * 128;
    const int NCH = K / 32;

    float acc[2][8][4];
#pragma unroll
    for (int mt = 0; mt < 2; mt++)
#pragma unroll
        for (int nt = 0; nt < 8; nt++)
#pragma unroll
            for (int j = 0; j < 4; j++) acc[mt][nt][j] = 0.f;

    auto fill = [&](int c, int stg) {
        const uint32_t s = sb + stg * GS_STAGE;
        const int k0 = c * 32;
#pragma unroll
        for (int i = 0; i < 2; i++) {
            int ch = tid + i * 256;
            int row = ch >> 2, part = ch & 3;
            int gm = bm + row;
            int sz = (gm < M) ? 16 : 0;
            int gmc = (gm < M) ? gm : 0;
            size_t go = (size_t)gmc * K + k0 + part * 8;
            cp16(s + OFF_AH_ + row * 80 + part * 16, Ah + go, sz);
            cp16(s + OFF_AL_ + row * 80 + part * 16, Al + go, sz);
        }
#pragma unroll
        for (int i = 0; i < 2; i++) {
            int ch = tid + i * 256;
            int kk = ch >> 4, nc = ch & 15;
            size_t go = (size_t)(k0 + kk) * N + bn + nc * 8;
            cp16(s + OFF_BH_ + kk * 272 + nc * 16, Bh + go, 16);
            cp16(s + OFF_BL_ + kk * 272 + nc * 16, Bl + go, 16);
        }
    };

    auto compute = [&](int stg) {
        const uint32_t base = sb + stg * GS_STAGE;
#pragma unroll
        for (int ks = 0; ks < 2; ks++) {
            uint32_t a_hi[2][4], a_lo[2][4];
            int arow = wm * 32 + (lane & 7) + ((lane >> 3) & 1) * 8;
            int acol = ks * 16 + (lane >> 4) * 8;
#pragma unroll
            for (int mt = 0; mt < 2; mt++) {
                uint32_t ao = (uint32_t)((arow + mt * 16) * 80 + acol * 2);
                ldm_x4(a_hi[mt], base + OFF_AH_ + ao);
                ldm_x4(a_lo[mt], base + OFF_AL_ + ao);
            }
            int krow = ks * 16 + (lane & 7) + ((lane >> 3) & 1) * 8;
#pragma unroll
            for (int g = 0; g < 4; g++) {
                int ncol = wn * 64 + g * 16 + (lane >> 4) * 8;
                uint32_t bo = (uint32_t)(krow * 272 + ncol * 2);
                uint32_t th[4], tl[4];
                ldm_x4_t(th, base + OFF_BH_ + bo);
                ldm_x4_t(tl, base + OFF_BL_ + bo);
#pragma unroll
                for (int mt = 0; mt < 2; mt++) {
                    mma_bf16(acc[mt][2 * g],     a_hi[mt], th);
                    mma_bf16(acc[mt][2 * g],     a_hi[mt], tl);
                    mma_bf16(acc[mt][2 * g],     a_lo[mt], th);
                    mma_bf16(acc[mt][2 * g + 1], a_hi[mt], th + 2);
                    mma_bf16(acc[mt][2 * g + 1], a_hi[mt], tl + 2);
                    mma_bf16(acc[mt][2 * g + 1], a_lo[mt], th + 2);
                }
            }
        }
    };

    // ---- 3-stage pipeline, one sync per chunk ----
    fill(0, 0);
    cp_commit();
    if (NCH > 1) { fill(1, 1); cp_commit(); }
    for (int c = 0; c < NCH; c++) {
        if (c + 1 < NCH) cp_wait<1>(); else cp_wait<0>();
        __syncthreads();
        compute(c % 3);
        if (c + 2 < NCH) { fill(c + 2, (c + 2) % 3); cp_commit(); }
    }

    // ---- epilogue (stats buffer reuses stage-0 smem) ----
    float* ssum = (float*)(smem);
    float* ssq  = (float*)(smem + 512);
    if (MODE == 1) {
        __syncthreads();
        if (tid < 128) { ssum[tid] = 0.f; ssq[tid] = 0.f; }
        __syncthreads();
    }
#pragma unroll
    for (int mt = 0; mt < 2; mt++) {
        int row = bm + wm * 32 + mt * 16 + (lane >> 2);
#pragma unroll
        for (int nt = 0; nt < 8; nt++) {
            int col = bn + wn * 64 + nt * 8 + (lane & 3) * 2;
            float b0 = bias[col], b1 = bias[col + 1];
            float v00 = acc[mt][nt][0] + b0, v01 = acc[mt][nt][1] + b1;
            float v10 = acc[mt][nt][2] + b0, v11 = acc[mt][nt][3] + b1;
            if (MODE == 0) {
                v00 = fmaxf(v00, 0.f); v01 = fmaxf(v01, 0.f);
                v10 = fmaxf(v10, 0.f); v11 = fmaxf(v11, 0.f);
                if (row < M) {
                    *(uint32_t*)(Oh + (size_t)row * N + col) = pack_hi(v00, v01);
                    *(uint32_t*)(Ol + (size_t)row * N + col) = pack_lo(v00, v01);
                }
                if (row + 8 < M) {
                    *(uint32_t*)(Oh + (size_t)(row + 8) * N + col) = pack_hi(v10, v11);
                    *(uint32_t*)(Ol + (size_t)(row + 8) * N + col) = pack_lo(v10, v11);
                }
            } else {
                int lc = col - bn;
                if (row < M) {
                    *(float2*)(Of + (size_t)row * N + col) = make_float2(v00, v01);
                    atomicAdd(&ssum[lc], v00);       atomicAdd(&ssum[lc + 1], v01);
                    atomicAdd(&ssq[lc], v00 * v00);  atomicAdd(&ssq[lc + 1], v01 * v01);
                }
                if (row + 8 < M) {
                    *(float2*)(Of + (size_t)(row + 8) * N + col) = make_float2(v10, v11);
                    atomicAdd(&ssum[lc], v10);       atomicAdd(&ssum[lc + 1], v11);
                    atomicAdd(&ssq[lc], v10 * v10);  atomicAdd(&ssq[lc + 1], v11 * v11);
                }
            }
        }
    }
    if (MODE == 1) {
        __syncthreads();
        if (tid < 128) {
            atomicAdd(&g_sum[tid], (double)ssum[tid]);
            atomicAdd(&g_sumsq[tid], (double)ssq[tid]);
        }
    }
}

// ---------------- W split ----------------
__global__ void wsplit_kernel(const float* __restrict__ w,
                              __nv_bfloat16* __restrict__ wh,
                              __nv_bfloat16* __restrict__ wl, int n)
{
    int i = blockIdx.x * blockDim.x + threadIdx.x;
    if (i >= n) return;
    float x = w[i];
    __nv_bfloat16 h = __float2bfloat16(x);
    wh[i] = h;
    wl[i] = __float2bfloat16(x - __bfloat162float(h));
}

// ---------------- seed (+ zero degree counters) ----------------
__global__ void seed_kernel(
    const int* __restrict__ an, const int* __restrict__ fc, const int* __restrict__ ct,
    const int* __restrict__ hy, const int* __restrict__ nh, const int* __restrict__ ar,
    const float* __restrict__ Ean, const float* __restrict__ Efc, const float* __restrict__ Ect,
    const float* __restrict__ Ehy, const float* __restrict__ Enh, const float* __restrict__ Ear)
{
    int gt = blockIdx.x * blockDim.x + threadIdx.x;
    if (gt < NN) g_cursor[gt] = 0;
    int w = gt >> 5;
    if (w >= NN) return;
    int d = (threadIdx.x & 31) * 4;
    float4 v = ld4(Ean + (size_t)an[w] * DD + d);
    add4(v, ld4(Efc + (size_t)fc[w] * DD + d));
    add4(v, ld4(Ect + (size_t)ct[w] * DD + d));
    add4(v, ld4(Ehy + (size_t)hy[w] * DD + d));
    add4(v, ld4(Enh + (size_t)nh[w] * DD + d));
    add4(v, ld4(Ear + (size_t)ar[w] * DD + d));
    *reinterpret_cast<float4*>(g_h + (size_t)w * DD + d) = v;
}

// ---------------- CSR build ----------------
__global__ void deg_count_kernel(const int* __restrict__ dst) {
    int e = blockIdx.x * blockDim.x + threadIdx.x;
    if (e < EE) atomicAdd(&g_cursor[dst[e]], 1);
}
__global__ void scan_chunks_kernel() {
    __shared__ int s[1024];
    int i = blockIdx.x * 1024 + threadIdx.x;
    int v = (i < NN) ? g_cursor[i] : 0;
    s[threadIdx.x] = v;
    __syncthreads();
#pragma unroll
    for (int off = 1; off < 1024; off <<= 1) {
        int x = (threadIdx.x >= off) ? s[threadIdx.x - off] : 0;
        __syncthreads();
        s[threadIdx.x] += x;
        __syncthreads();
    }
    if (i < NN) g_offs[i] = s[threadIdx.x] - v;
    if (threadIdx.x == 1023) g_chunksums[blockIdx.x] = s[1023];
}
__global__ void scan_apply_kernel() {
    __shared__ int base_s;
    if (threadIdx.x == 0) {
        int myChunk = (blockIdx.x * 256) >> 10;
        int b = 0;
        for (int i = 0; i < myChunk; i++) b += g_chunksums[i];
        base_s = b;
    }
    __syncthreads();
    int i = blockIdx.x * 256 + threadIdx.x;
    if (i < NN) {
        int o = g_offs[i] + base_s;
        g_offs[i] = o;
        g_cursor[i] = o;
    }
    if (i == 0) g_offs[NN] = EE;
}

static __device__ __forceinline__ void combo_row(
    int w, int d,
    const float* __restrict__ ec, const float* __restrict__ ea,
    const float* __restrict__ eb, const float* __restrict__ ed,
    const float* __restrict__ es, float* __restrict__ out)
{
    int c = w;
    int vbs = c % 6; c /= 6;
    int vbd = c % 7; c /= 7;
    int vbt = c % 22; c /= 22;
    int via = c & 1;
    int vic = c >> 1;
    float4 v = ld4(ec + (size_t)vic * DD + d);
    add4(v, ld4(ea + (size_t)via * DD + d));
    add4(v, ld4(eb + (size_t)vbt * DD + d));
    add4(v, ld4(ed + (size_t)vbd * DD + d));
    add4(v, ld4(es + (size_t)vbs * DD + d));
    *reinterpret_cast<float4*>(out + (size_t)w * DD + d) = v;
}

// csr_fill + layer-0 combo table, fused (disjoint block ranges)
__global__ void csr_fill_combo_kernel(
    const int* __restrict__ src, const int* __restrict__ dst,
    const int* __restrict__ ic, const int* __restrict__ ia,
    const int* __restrict__ bt, const int* __restrict__ bd,
    const int* __restrict__ bs,
    const float* __restrict__ ec, const float* __restrict__ ea,
    const float* __restrict__ eb, const float* __restrict__ ed,
    const float* __restrict__ es, int edge_blocks)
{
    if ((int)blockIdx.x < edge_blocks) {
        int e = blockIdx.x * 256 + threadIdx.x;
        if (e >= EE) return;
        int pos = atomicAdd(&g_cursor[dst[e]], 1);
        int c = (((ic[e] * 2 + ia[e]) * 22 + bt[e]) * 7 + bd[e]) * 6 + bs[e];
        g_edge_data[pos] = make_int2(src[e], c);
    } else {
        int w = ((blockIdx.x - edge_blocks) * 256 + threadIdx.x) >> 5;
        if (w >= COMBO) return;
        combo_row(w, (threadIdx.x & 31) * 4, ec, ea, eb, ed, es, g_combo);
    }
}

// per-layer combo table (layers >= 1)
__global__ void combo_build_kernel(
    const float* __restrict__ ec, const float* __restrict__ ea,
    const float* __restrict__ eb, const float* __restrict__ ed,
    const float* __restrict__ es)
{
    int w = (blockIdx.x * blockDim.x + threadIdx.x) >> 5;
    if (w >= COMBO) return;
    combo_row(w, (threadIdx.x & 31) * 4, ec, ea, eb, ed, es, g_combo);
}

// ---------------- aggregation: gather + bf16 split output ----------------
__global__ void aggregate_kernel() {
    int w = (blockIdx.x * blockDim.x + threadIdx.x) >> 5;
    if (w >= NN) return;
    int d = (threadIdx.x & 31) * 4;
    float4 v = ld4(g_h + (size_t)w * DD + d);
    add4(v, ld4(g_combo + d));
    int beg = g_offs[w], end = g_offs[w + 1];
    for (int i = beg; i < end; i++) {
        int2 ed = g_edge_data[i];
        add4(v, ld4(g_h + (size_t)ed.x * DD + d));
        add4(v, ld4(g_combo + (size_t)ed.y * DD + d));
    }
    uint2 hi, lo;
    hi.x = pack_hi(v.x, v.y); hi.y = pack_hi(v.z, v.w);
    lo.x = pack_lo(v.x, v.y); lo.y = pack_lo(v.z, v.w);
    *(uint2*)(g_agg_h + (size_t)w * DD + d) = hi;
    *(uint2*)(g_agg_l + (size_t)w * DD + d) = lo;
}

// ---------------- batch norm ----------------
__global__ void zero_stats_kernel() {
    int d = threadIdx.x;
    if (d < DD) { g_sum[d] = 0.0; g_sumsq[d] = 0.0; }
}
__global__ void bn_finalize_kernel(
    const float* __restrict__ gamma, const float* __restrict__ beta)
{
    int d = threadIdx.x;
    if (d < DD) {
        double m = g_sum[d] / (double)NN;
        double var = g_sumsq[d] / (double)NN - m * m;
        float sc = gamma[d] * rsqrtf((float)var + BN_EPS);
        g_scale[d] = sc;
        g_shift[d] = beta[d] - sc * (float)m;
    }
}
__global__ void bn_apply_kernel(
    const float* __restrict__ x, float* __restrict__ out, int relu)
{
    int i = blockIdx.x * blockDim.x + threadIdx.x;
    if (i >= NN * DD / 4) return;
    int d = (i & (DD / 4 - 1)) * 4;
    float4 v = ld4(x + (size_t)i * 4);
    float4 sc = ld4(g_scale + d);
    float4 sh = ld4(g_shift + d);
    v.x = fmaf(sc.x, v.x, sh.x);
    v.y = fmaf(sc.y, v.y, sh.y);
    v.z = fmaf(sc.z, v.z, sh.z);
    v.w = fmaf(sc.w, v.w, sh.w);
    if (relu) {
        v.x = fmaxf(v.x, 0.f); v.y = fmaxf(v.y, 0.f);
        v.z = fmaxf(v.z, 0.f); v.w = fmaxf(v.w, 0.f);
    }
    *reinterpret_cast<float4*>(out + (size_t)i * 4) = v;
}

// ---------------- host launcher ----------------
extern "C" void kernel_launch(void* const* d_in, const int* in_sizes, int n_in,
                              void* d_out, int out_size)
{
    const int* atomic_num      = (const int*)d_in[0];
    const int* formal_charge   = (const int*)d_in[1];
    const int* chiral_tag      = (const int*)d_in[2];
    const int* hybridization   = (const int*)d_in[3];
    const int* num_explicit_hs = (const int*)d_in[4];
    const int* is_aromatic     = (const int*)d_in[5];
    const int* edge_index      = (const int*)d_in[6];
    const int* is_conjugated   = (const int*)d_in[7];
    const int* edge_is_arom    = (const int*)d_in[8];
    const int* bond_type       = (const int*)d_in[9];
    const int* bond_dir        = (const int*)d_in[10];
    const int* bond_stereo     = (const int*)d_in[11];
    const float* emb_atomic_num      = (const float*)d_in[12];
    const float* emb_formal_charge   = (const float*)d_in[13];
    const float* emb_chiral_tag      = (const float*)d_in[14];
    const float* emb_hybridization   = (const float*)d_in[15];
    const float* emb_num_explicit_hs = (const float*)d_in[16];
    const float* emb_is_aromatic     = (const float*)d_in[17];
    const float* e_conj    = (const float*)d_in[18];
    const float* e_arom    = (const float*)d_in[19];
    const float* e_btype   = (const float*)d_in[20];
    const float* e_bdir    = (const float*)d_in[21];
    const float* e_bstereo = (const float*)d_in[22];
    const float* mlp_w1 = (const float*)d_in[23];
    const float* mlp_b1 = (const float*)d_in[24];
    const float* mlp_w2 = (const float*)d_in[25];
    const float* mlp_b2 = (const float*)d_in[26];
    const float* bn_gamma = (const float*)d_in[27];
    const float* bn_beta  = (const float*)d_in[28];

    const int* src = edge_index;
    const int* dst = edge_index + EE;

    float* h_ptr; cudaGetSymbolAddress((void**)&h_ptr, g_h);
    __nv_bfloat16 *aggh, *aggl, *hidh, *hidl, *w1h, *w1l, *w2h, *w2l;
    cudaGetSymbolAddress((void**)&aggh, g_agg_h);
    cudaGetSymbolAddress((void**)&aggl, g_agg_l);
    cudaGetSymbolAddress((void**)&hidh, g_hid_h);
    cudaGetSymbolAddress((void**)&hidl, g_hid_l);
    cudaGetSymbolAddress((void**)&w1h, g_w1h);
    cudaGetSymbolAddress((void**)&w1l, g_w1l);
    cudaGetSymbolAddress((void**)&w2h, g_w2h);
    cudaGetSymbolAddress((void**)&w2l, g_w2l);

    cudaFuncSetAttribute(hsplit_gemm<256, 128, 0>,
                         cudaFuncAttributeMaxDynamicSharedMemorySize, GEMM_SMEM);
    cudaFuncSetAttribute(hsplit_gemm<128, 256, 1>,
                         cudaFuncAttributeMaxDynamicSharedMemorySize, GEMM_SMEM);

    const int warp_node_blocks  = (NN * 32 + 255) / 256;
    const int warp_combo_blocks = (COMBO * 32 + 255) / 256;
    const int edge_blocks = (EE + 255) / 256;
    const int node_blocks = (NN + 255) / 256;
    const int mtiles = (NN + 127) / 128;

    // #1 seed
    seed_kernel<<<warp_node_blocks, 256>>>(
        atomic_num, formal_charge, chiral_tag, hybridization,
        num_explicit_hs, is_aromatic,
        emb_atomic_num, emb_formal_charge, emb_chiral_tag,
        emb_hybridization, emb_num_explicit_hs, emb_is_aromatic);

    // #2, #3
    deg_count_kernel<<<edge_blocks, 256>>>(dst);
    scan_chunks_kernel<<<NCHUNK, 1024>>>();

    // #4 DIAGNOSTIC: dummy aggregate so ncu's fixed capture window profiles it.
    // Reads g_h (seeded) + steady-state CSR/combo data (identical on every
    // timed replay; zeros on the first correctness call). Writes g_agg_* which
    // the real aggregate below fully overwrites -> output invariant.
    aggregate_kernel<<<warp_node_blocks, 256>>>();

    // #5, #6
    scan_apply_kernel<<<node_blocks, 256>>>();
    csr_fill_combo_kernel<<<edge_blocks + warp_combo_blocks, 256>>>(
        src, dst, is_conjugated, edge_is_arom, bond_type, bond_dir, bond_stereo,
        e_conj, e_arom, e_btype, e_bdir, e_bstereo, edge_blocks);

    for (int l = 0; l < LL; l++) {
        if (l > 0) {
            combo_build_kernel<<<warp_combo_blocks, 256>>>(
                e_conj    + (size_t)l * 3 * DD,
                e_arom    + (size_t)l * 3 * DD,
                e_btype   + (size_t)l * 23 * DD,
                e_bdir    + (size_t)l * 8 * DD,
                e_bstereo + (size_t)l * 7 * DD);
        }

        aggregate_kernel<<<warp_node_blocks, 256>>>();

        wsplit_kernel<<<(DD * 2 * DD + 255) / 256, 256>>>(
            mlp_w1 + (size_t)l * DD * 2 * DD, w1h, w1l, DD * 2 * DD);
        wsplit_kernel<<<(2 * DD * DD + 255) / 256, 256>>>(
            mlp_w2 + (size_t)l * 2 * DD * DD, w2h, w2l, 2 * DD * DD);

        {
            dim3 grid(2, mtiles);
            hsplit_gemm<256, 128, 0><<<grid, 256, GEMM_SMEM>>>(
                aggh, aggl, w1h, w1l,
                mlp_b1 + (size_t)l * 2 * DD, hidh, hidl, nullptr, NN);
        }
        zero_stats_kernel<<<1, 128>>>();
        {
            dim3 grid(1, mtiles);
            hsplit_gemm<128, 256, 1><<<grid, 256, GEMM_SMEM>>>(
                hidh, hidl, w2h, w2l,
                mlp_b2 + (size_t)l * DD, nullptr, nullptr, h_ptr, NN);
        }

        bn_finalize_kernel<<<1, 128>>>(
            bn_gamma + (size_t)l * DD, bn_beta + (size_t)l * DD);

        float* out = (l == LL - 1) ? (float*)d_out : h_ptr;
        bn_apply_kernel<<<(NN * DD / 4 + 255) / 256, 256>>>(
            h_ptr, out, (l < LL - 1) ? 1 : 0);
    }
}

// round 14
// speedup vs baseline: 56.8555x; 56.8555x over previous
#include <cuda_runtime.h>
#include <cuda_bf16.h>
#include <math.h>
#include <cstdint>

#define NN 100000
#define EE 600000
#define DD 128
#define LL 5
#define BN_EPS 1e-5f
#define COMBO 7392
#define NCHUNK ((NN + 1023) / 1024)
#define COMBO_BLOCKS ((COMBO * 32 + 255) / 256)   // 924
#define WS_BLOCKS 128                              // 32768 / 256 per weight

// ---------------- device scratch ----------------
__device__ float  g_h[(size_t)NN * DD];
__device__ __nv_bfloat16 g_agg_h[(size_t)NN * DD];
__device__ __nv_bfloat16 g_agg_l[(size_t)NN * DD];
__device__ __nv_bfloat16 g_hid_h[(size_t)NN * 2 * DD];
__device__ __nv_bfloat16 g_hid_l[(size_t)NN * 2 * DD];
__device__ __nv_bfloat16 g_w1h[DD * 2 * DD];
__device__ __nv_bfloat16 g_w1l[DD * 2 * DD];
__device__ __nv_bfloat16 g_w2h[2 * DD * DD];
__device__ __nv_bfloat16 g_w2l[2 * DD * DD];
__device__ float  g_combo[(size_t)COMBO * DD];
__device__ int    g_offs[NN + 1];
__device__ int    g_cursor[NN];
__device__ int    g_chunksums[NCHUNK];
__device__ int2   g_edge_data[EE];
__device__ double g_sum[DD];
__device__ double g_sumsq[DD];

static __device__ __forceinline__ float4 ld4(const float* p) {
    return *reinterpret_cast<const float4*>(p);
}
static __device__ __forceinline__ void add4(float4& a, const float4 b) {
    a.x += b.x; a.y += b.y; a.z += b.z; a.w += b.w;
}

// ================= MMA helpers =================
static __device__ __forceinline__ uint32_t smem_u32(const void* p) {
    uint32_t a;
    asm("{ .reg .u64 t; cvta.to.shared.u64 t, %1; cvt.u32.u64 %0, t; }" : "=r"(a) : "l"(p));
    return a;
}
static __device__ __forceinline__ void ldm_x4(uint32_t* r, uint32_t addr) {
    asm volatile("ldmatrix.sync.aligned.m8n8.x4.shared.b16 {%0,%1,%2,%3}, [%4];"
        : "=r"(r[0]), "=r"(r[1]), "=r"(r[2]), "=r"(r[3]) : "r"(addr));
}
static __device__ __forceinline__ void ldm_x4_t(uint32_t* r, uint32_t addr) {
    asm volatile("ldmatrix.sync.aligned.m8n8.x4.trans.shared.b16 {%0,%1,%2,%3}, [%4];"
        : "=r"(r[0]), "=r"(r[1]), "=r"(r[2]), "=r"(r[3]) : "r"(addr));
}
static __device__ __forceinline__ void mma_bf16(float* d, const uint32_t* a, const uint32_t* b) {
    asm volatile(
        "mma.sync.aligned.m16n8k16.row.col.f32.bf16.bf16.f32 "
        "{%0,%1,%2,%3}, {%4,%5,%6,%7}, {%8,%9}, {%0,%1,%2,%3};"
        : "+f"(d[0]), "+f"(d[1]), "+f"(d[2]), "+f"(d[3])
        : "r"(a[0]), "r"(a[1]), "r"(a[2]), "r"(a[3]), "r"(b[0]), "r"(b[1]));
}
static __device__ __forceinline__ void cp16(uint32_t dst, const void* src, int sz) {
    asm volatile("cp.async.cg.shared.global [%0], [%1], 16, %2;"
        :: "r"(dst), "l"(src), "r"(sz) : "memory");
}
static __device__ __forceinline__ void cp_commit() {
    asm volatile("cp.async.commit_group;" ::: "memory");
}
template <int Nk>
static __device__ __forceinline__ void cp_wait() {
    asm volatile("cp.async.wait_group %0;" :: "n"(Nk) : "memory");
}

// smem stage layout (bytes): A rows 80B stride, B rows 272B stride. 3 stages.
#define OFF_AH_ 0
#define OFF_AL_ 10240
#define OFF_BH_ 20480
#define OFF_BL_ 29184
#define GS_STAGE 37888
#define GEMM_SMEM (3 * GS_STAGE)

static __device__ __forceinline__ uint32_t pack_hi(float v0, float v1) {
    unsigned short h0 = __bfloat16_as_ushort(__float2bfloat16(v0));
    unsigned short h1 = __bfloat16_as_ushort(__float2bfloat16(v1));
    return (uint32_t)h0 | ((uint32_t)h1 << 16);
}
static __device__ __forceinline__ uint32_t pack_lo(float v0, float v1) {
    float f0 = __bfloat162float(__float2bfloat16(v0));
    float f1 = __bfloat162float(__float2bfloat16(v1));
    unsigned short l0 = __bfloat16_as_ushort(__float2bfloat16(v0 - f0));
    unsigned short l1 = __bfloat16_as_ushort(__float2bfloat16(v1 - f1));
    return (uint32_t)l0 | ((uint32_t)l1 << 16);
}

// MODE 0: relu, write bf16 hi/lo (Oh/Ol). MODE 1: no relu, write fp32 Of + column stats.
template <int N, int K, int MODE>
__global__ __launch_bounds__(256, 2) void hsplit_gemm(
    const __nv_bfloat16* __restrict__ Ah, const __nv_bfloat16* __restrict__ Al,
    const __nv_bfloat16* __restrict__ Bh, const __nv_bfloat16* __restrict__ Bl,
    const float* __restrict__ bias,
    __nv_bfloat16* __restrict__ Oh, __nv_bfloat16* __restrict__ Ol,
    float* __restrict__ Of, int M)
{
    extern __shared__ char smem[];
    const uint32_t sb = smem_u32(smem);
    const int tid = threadIdx.x;
    const int lane = tid & 31;
    const int w = tid >> 5;
    const int wm = w & 3;
    const int wn = w >> 2;
    const int bm = blockIdx.y * 128;
    const int bn = blockIdx.x * 128;
    const int NCH = K / 32;

    float acc[2][8][4];
#pragma unroll
    for (int mt = 0; mt < 2; mt++)
#pragma unroll
        for (int nt = 0; nt < 8; nt++)
#pragma unroll
            for (int j = 0; j < 4; j++) acc[mt][nt][j] = 0.f;

    auto fill = [&](int c, int stg) {
        const uint32_t s = sb + stg * GS_STAGE;
        const int k0 = c * 32;
#pragma unroll
        for (int i = 0; i < 2; i++) {
            int ch = tid + i * 256;
            int row = ch >> 2, part = ch & 3;
            int gm = bm + row;
            int sz = (gm < M) ? 16 : 0;
            int gmc = (gm < M) ? gm : 0;
            size_t go = (size_t)gmc * K + k0 + part * 8;
            cp16(s + OFF_AH_ + row * 80 + part * 16, Ah + go, sz);
            cp16(s + OFF_AL_ + row * 80 + part * 16, Al + go, sz);
        }
#pragma unroll
        for (int i = 0; i < 2; i++) {
            int ch = tid + i * 256;
            int kk = ch >> 4, nc = ch & 15;
            size_t go = (size_t)(k0 + kk) * N + bn + nc * 8;
            cp16(s + OFF_BH_ + kk * 272 + nc * 16, Bh + go, 16);
            cp16(s + OFF_BL_ + kk * 272 + nc * 16, Bl + go, 16);
        }
    };

    auto compute = [&](int stg) {
        const uint32_t base = sb + stg * GS_STAGE;
#pragma unroll
        for (int ks = 0; ks < 2; ks++) {
            uint32_t a_hi[2][4], a_lo[2][4];
            int arow = wm * 32 + (lane & 7) + ((lane >> 3) & 1) * 8;
            int acol = ks * 16 + (lane >> 4) * 8;
#pragma unroll
            for (int mt = 0; mt < 2; mt++) {
                uint32_t ao = (uint32_t)((arow + mt * 16) * 80 + acol * 2);
                ldm_x4(a_hi[mt], base + OFF_AH_ + ao);
                ldm_x4(a_lo[mt], base + OFF_AL_ + ao);
            }
            int krow = ks * 16 + (lane & 7) + ((lane >> 3) & 1) * 8;
#pragma unroll
            for (int g = 0; g < 4; g++) {
                int ncol = wn * 64 + g * 16 + (lane >> 4) * 8;
                uint32_t bo = (uint32_t)(krow * 272 + ncol * 2);
                uint32_t th[4], tl[4];
                ldm_x4_t(th, base + OFF_BH_ + bo);
                ldm_x4_t(tl, base + OFF_BL_ + bo);
#pragma unroll
                for (int mt = 0; mt < 2; mt++) {
                    mma_bf16(acc[mt][2 * g],     a_hi[mt], th);
                    mma_bf16(acc[mt][2 * g],     a_hi[mt], tl);
                    mma_bf16(acc[mt][2 * g],     a_lo[mt], th);
                    mma_bf16(acc[mt][2 * g + 1], a_hi[mt], th + 2);
                    mma_bf16(acc[mt][2 * g + 1], a_hi[mt], tl + 2);
                    mma_bf16(acc[mt][2 * g + 1], a_lo[mt], th + 2);
                }
            }
        }
    };

    // ---- 3-stage pipeline, one sync per chunk ----
    fill(0, 0);
    cp_commit();
    if (NCH > 1) { fill(1, 1); cp_commit(); }
    for (int c = 0; c < NCH; c++) {
        if (c + 1 < NCH) cp_wait<1>(); else cp_wait<0>();
        __syncthreads();
        compute(c % 3);
        if (c + 2 < NCH) { fill(c + 2, (c + 2) % 3); cp_commit(); }
    }

    // ---- epilogue (stats buffer reuses stage-0 smem) ----
    float* ssum = (float*)(smem);
    float* ssq  = (float*)(smem + 512);
    if (MODE == 1) {
        __syncthreads();
        if (tid < 128) { ssum[tid] = 0.f; ssq[tid] = 0.f; }
        __syncthreads();
    }
#pragma unroll
    for (int mt = 0; mt < 2; mt++) {
        int row = bm + wm * 32 + mt * 16 + (lane >> 2);
#pragma unroll
        for (int nt = 0; nt < 8; nt++) {
            int col = bn + wn * 64 + nt * 8 + (lane & 3) * 2;
            float b0 = bias[col], b1 = bias[col + 1];
            float v00 = acc[mt][nt][0] + b0, v01 = acc[mt][nt][1] + b1;
            float v10 = acc[mt][nt][2] + b0, v11 = acc[mt][nt][3] + b1;
            if (MODE == 0) {
                v00 = fmaxf(v00, 0.f); v01 = fmaxf(v01, 0.f);
                v10 = fmaxf(v10, 0.f); v11 = fmaxf(v11, 0.f);
                if (row < M) {
                    *(uint32_t*)(Oh + (size_t)row * N + col) = pack_hi(v00, v01);
                    *(uint32_t*)(Ol + (size_t)row * N + col) = pack_lo(v00, v01);
                }
                if (row + 8 < M) {
                    *(uint32_t*)(Oh + (size_t)(row + 8) * N + col) = pack_hi(v10, v11);
                    *(uint32_t*)(Ol + (size_t)(row + 8) * N + col) = pack_lo(v10, v11);
                }
            } else {
                int lc = col - bn;
                if (row < M) {
                    *(float2*)(Of + (size_t)row * N + col) = make_float2(v00, v01);
                    atomicAdd(&ssum[lc], v00);       atomicAdd(&ssum[lc + 1], v01);
                    atomicAdd(&ssq[lc], v00 * v00);  atomicAdd(&ssq[lc + 1], v01 * v01);
                }
                if (row + 8 < M) {
                    *(float2*)(Of + (size_t)(row + 8) * N + col) = make_float2(v10, v11);
                    atomicAdd(&ssum[lc], v10);       atomicAdd(&ssum[lc + 1], v11);
                    atomicAdd(&ssq[lc], v10 * v10);  atomicAdd(&ssq[lc + 1], v11 * v11);
                }
            }
        }
    }
    if (MODE == 1) {
        __syncthreads();
        if (tid < 128) {
            atomicAdd(&g_sum[tid], (double)ssum[tid]);
            atomicAdd(&g_sumsq[tid], (double)ssq[tid]);
        }
    }
}

// ---------------- seed (+ zero degree counters) ----------------
__global__ void seed_kernel(
    const int* __restrict__ an, const int* __restrict__ fc, const int* __restrict__ ct,
    const int* __restrict__ hy, const int* __restrict__ nh, const int* __restrict__ ar,
    const float* __restrict__ Ean, const float* __restrict__ Efc, const float* __restrict__ Ect,
    const float* __restrict__ Ehy, const float* __restrict__ Enh, const float* __restrict__ Ear)
{
    int gt = blockIdx.x * blockDim.x + threadIdx.x;
    if (gt < NN) g_cursor[gt] = 0;
    int w = gt >> 5;
    if (w >= NN) return;
    int d = (threadIdx.x & 31) * 4;
    float4 v = ld4(Ean + (size_t)an[w] * DD + d);
    add4(v, ld4(Efc + (size_t)fc[w] * DD + d));
    add4(v, ld4(Ect + (size_t)ct[w] * DD + d));
    add4(v, ld4(Ehy + (size_t)hy[w] * DD + d));
    add4(v, ld4(Enh + (size_t)nh[w] * DD + d));
    add4(v, ld4(Ear + (size_t)ar[w] * DD + d));
    *reinterpret_cast<float4*>(g_h + (size_t)w * DD + d) = v;
}

// ---------------- CSR build ----------------
__global__ void deg_count_kernel(const int* __restrict__ dst) {
    int e = blockIdx.x * blockDim.x + threadIdx.x;
    if (e < EE) atomicAdd(&g_cursor[dst[e]], 1);
}
__global__ void scan_chunks_kernel() {
    __shared__ int s[1024];
    int i = blockIdx.x * 1024 + threadIdx.x;
    int v = (i < NN) ? g_cursor[i] : 0;
    s[threadIdx.x] = v;
    __syncthreads();
#pragma unroll
    for (int off = 1; off < 1024; off <<= 1) {
        int x = (threadIdx.x >= off) ? s[threadIdx.x - off] : 0;
        __syncthreads();
        s[threadIdx.x] += x;
        __syncthreads();
    }
    if (i < NN) g_offs[i] = s[threadIdx.x] - v;
    if (threadIdx.x == 1023) g_chunksums[blockIdx.x] = s[1023];
}
__global__ void scan_apply_kernel() {
    __shared__ int base_s;
    if (threadIdx.x == 0) {
        int myChunk = (blockIdx.x * 256) >> 10;
        int b = 0;
        for (int i = 0; i < myChunk; i++) b += g_chunksums[i];
        base_s = b;
    }
    __syncthreads();
    int i = blockIdx.x * 256 + threadIdx.x;
    if (i < NN) {
        int o = g_offs[i] + base_s;
        g_offs[i] = o;
        g_cursor[i] = o;
    }
    if (i == 0) g_offs[NN] = EE;
}

static __device__ __forceinline__ void combo_row(
    int w, int d,
    const float* __restrict__ ec, const float* __restrict__ ea,
    const float* __restrict__ eb, const float* __restrict__ ed,
    const float* __restrict__ es, float* __restrict__ out)
{
    int c = w;
    int vbs = c % 6; c /= 6;
    int vbd = c % 7; c /= 7;
    int vbt = c % 22; c /= 22;
    int via = c & 1;
    int vic = c >> 1;
    float4 v = ld4(ec + (size_t)vic * DD + d);
    add4(v, ld4(ea + (size_t)via * DD + d));
    add4(v, ld4(eb + (size_t)vbt * DD + d));
    add4(v, ld4(ed + (size_t)vbd * DD + d));
    add4(v, ld4(es + (size_t)vbs * DD + d));
    *reinterpret_cast<float4*>(out + (size_t)w * DD + d) = v;
}

// csr_fill + layer-0 combo table, fused (disjoint block ranges)
__global__ void csr_fill_combo_kernel(
    const int* __restrict__ src, const int* __restrict__ dst,
    const int* __restrict__ ic, const int* __restrict__ ia,
    const int* __restrict__ bt, const int* __restrict__ bd,
    const int* __restrict__ bs,
    const float* __restrict__ ec, const float* __restrict__ ea,
    const float* __restrict__ eb, const float* __restrict__ ed,
    const float* __restrict__ es, int edge_blocks)
{
    if ((int)blockIdx.x < edge_blocks) {
        int e = blockIdx.x * 256 + threadIdx.x;
        if (e >= EE) return;
        int pos = atomicAdd(&g_cursor[dst[e]], 1);
        int c = (((ic[e] * 2 + ia[e]) * 22 + bt[e]) * 7 + bd[e]) * 6 + bs[e];
        g_edge_data[pos] = make_int2(src[e], c);
    } else {
        int w = ((blockIdx.x - edge_blocks) * 256 + threadIdx.x) >> 5;
        if (w >= COMBO) return;
        combo_row(w, (threadIdx.x & 31) * 4, ec, ea, eb, ed, es, g_combo);
    }
}

// ---- per-layer prep: [combo (l>0)] | wsplit W1 | wsplit W2 | zero stats ----
// block ranges: [0, WS_BLOCKS) W1, [WS, 2*WS) W2, [2*WS, 2*WS+combo_blocks) combo
__global__ void prep_kernel(
    const float* __restrict__ w1, const float* __restrict__ w2,
    const float* __restrict__ ec, const float* __restrict__ ea,
    const float* __restrict__ eb, const float* __restrict__ ed,
    const float* __restrict__ es)
{
    const int bx = blockIdx.x;
    const int tid = threadIdx.x;
    if (bx < WS_BLOCKS) {
        if (bx == 0 && tid < DD) { g_sum[tid] = 0.0; g_sumsq[tid] = 0.0; }
        int i = bx * 256 + tid;
        float x = w1[i];
        __nv_bfloat16 h = __float2bfloat16(x);
        g_w1h[i] = h;
        g_w1l[i] = __float2bfloat16(x - __bfloat162float(h));
    } else if (bx < 2 * WS_BLOCKS) {
        int i = (bx - WS_BLOCKS) * 256 + tid;
        float x = w2[i];
        __nv_bfloat16 h = __float2bfloat16(x);
        g_w2h[i] = h;
        g_w2l[i] = __float2bfloat16(x - __bfloat162float(h));
    } else {
        int w = ((bx - 2 * WS_BLOCKS) * 256 + tid) >> 5;
        if (w >= COMBO) return;
        combo_row(w, (tid & 31) * 4, ec, ea, eb, ed, es, g_combo);
    }
}

// ---------------- aggregation: gather + bf16 split output ----------------
__global__ void aggregate_kernel() {
    int w = (blockIdx.x * blockDim.x + threadIdx.x) >> 5;
    if (w >= NN) return;
    int d = (threadIdx.x & 31) * 4;
    float4 v = ld4(g_h + (size_t)w * DD + d);
    add4(v, ld4(g_combo + d));
    int beg = g_offs[w], end = g_offs[w + 1];
    for (int i = beg; i < end; i++) {
        int2 ed = g_edge_data[i];
        add4(v, ld4(g_h + (size_t)ed.x * DD + d));
        add4(v, ld4(g_combo + (size_t)ed.y * DD + d));
    }
    uint2 hi, lo;
    hi.x = pack_hi(v.x, v.y); hi.y = pack_hi(v.z, v.w);
    lo.x = pack_lo(v.x, v.y); lo.y = pack_lo(v.z, v.w);
    *(uint2*)(g_agg_h + (size_t)w * DD + d) = hi;
    *(uint2*)(g_agg_l + (size_t)w * DD + d) = lo;
}

// ---------------- batch norm apply (finalize inlined per block) -------------
__global__ void bn_apply_kernel(
    const float* __restrict__ gamma, const float* __restrict__ beta,
    const float* __restrict__ x, float* __restrict__ out, int relu)
{
    __shared__ float ssc[DD];
    __shared__ float ssh[DD];
    if (threadIdx.x < DD) {
        int d = threadIdx.x;
        double m = g_sum[d] / (double)NN;
        double var = g_sumsq[d] / (double)NN - m * m;
        float sc = gamma[d] * rsqrtf((float)var + BN_EPS);
        ssc[d] = sc;
        ssh[d] = beta[d] - sc * (float)m;
    }
    __syncthreads();
    int i = blockIdx.x * blockDim.x + threadIdx.x;
    if (i >= NN * DD / 4) return;
    int d = (i & (DD / 4 - 1)) * 4;
    float4 v = ld4(x + (size_t)i * 4);
    float4 sc = *(float4*)(ssc + d);
    float4 sh = *(float4*)(ssh + d);
    v.x = fmaf(sc.x, v.x, sh.x);
    v.y = fmaf(sc.y, v.y, sh.y);
    v.z = fmaf(sc.z, v.z, sh.z);
    v.w = fmaf(sc.w, v.w, sh.w);
    if (relu) {
        v.x = fmaxf(v.x, 0.f); v.y = fmaxf(v.y, 0.f);
        v.z = fmaxf(v.z, 0.f); v.w = fmaxf(v.w, 0.f);
    }
    *reinterpret_cast<float4*>(out + (size_t)i * 4) = v;
}

// ---------------- host launcher ----------------
extern "C" void kernel_launch(void* const* d_in, const int* in_sizes, int n_in,
                              void* d_out, int out_size)
{
    const int* atomic_num      = (const int*)d_in[0];
    const int* formal_charge   = (const int*)d_in[1];
    const int* chiral_tag      = (const int*)d_in[2];
    const int* hybridization   = (const int*)d_in[3];
    const int* num_explicit_hs = (const int*)d_in[4];
    const int* is_aromatic     = (const int*)d_in[5];
    const int* edge_index      = (const int*)d_in[6];
    const int* is_conjugated   = (const int*)d_in[7];
    const int* edge_is_arom    = (const int*)d_in[8];
    const int* bond_type       = (const int*)d_in[9];
    const int* bond_dir        = (const int*)d_in[10];
    const int* bond_stereo     = (const int*)d_in[11];
    const float* emb_atomic_num      = (const float*)d_in[12];
    const float* emb_formal_charge   = (const float*)d_in[13];
    const float* emb_chiral_tag      = (const float*)d_in[14];
    const float* emb_hybridization   = (const float*)d_in[15];
    const float* emb_num_explicit_hs = (const float*)d_in[16];
    const float* emb_is_aromatic     = (const float*)d_in[17];
    const float* e_conj    = (const float*)d_in[18];
    const float* e_arom    = (const float*)d_in[19];
    const float* e_btype   = (const float*)d_in[20];
    const float* e_bdir    = (const float*)d_in[21];
    const float* e_bstereo = (const float*)d_in[22];
    const float* mlp_w1 = (const float*)d_in[23];
    const float* mlp_b1 = (const float*)d_in[24];
    const float* mlp_w2 = (const float*)d_in[25];
    const float* mlp_b2 = (const float*)d_in[26];
    const float* bn_gamma = (const float*)d_in[27];
    const float* bn_beta  = (const float*)d_in[28];

    const int* src = edge_index;
    const int* dst = edge_index + EE;

    float* h_ptr; cudaGetSymbolAddress((void**)&h_ptr, g_h);
    __nv_bfloat16 *aggh, *aggl, *hidh, *hidl, *w1h, *w1l, *w2h, *w2l;
    cudaGetSymbolAddress((void**)&aggh, g_agg_h);
    cudaGetSymbolAddress((void**)&aggl, g_agg_l);
    cudaGetSymbolAddress((void**)&hidh, g_hid_h);
    cudaGetSymbolAddress((void**)&hidl, g_hid_l);
    cudaGetSymbolAddress((void**)&w1h, g_w1h);
    cudaGetSymbolAddress((void**)&w1l, g_w1l);
    cudaGetSymbolAddress((void**)&w2h, g_w2h);
    cudaGetSymbolAddress((void**)&w2l, g_w2l);

    cudaFuncSetAttribute(hsplit_gemm<256, 128, 0>,
                         cudaFuncAttributeMaxDynamicSharedMemorySize, GEMM_SMEM);
    cudaFuncSetAttribute(hsplit_gemm<128, 256, 1>,
                         cudaFuncAttributeMaxDynamicSharedMemorySize, GEMM_SMEM);

    const int warp_node_blocks = (NN * 32 + 255) / 256;
    const int edge_blocks = (EE + 255) / 256;
    const int node_blocks = (NN + 255) / 256;
    const int mtiles = (NN + 127) / 128;

    seed_kernel<<<warp_node_blocks, 256>>>(
        atomic_num, formal_charge, chiral_tag, hybridization,
        num_explicit_hs, is_aromatic,
        emb_atomic_num, emb_formal_charge, emb_chiral_tag,
        emb_hybridization, emb_num_explicit_hs, emb_is_aromatic);

    deg_count_kernel<<<edge_blocks, 256>>>(dst);
    scan_chunks_kernel<<<NCHUNK, 1024>>>();
    scan_apply_kernel<<<node_blocks, 256>>>();
    csr_fill_combo_kernel<<<edge_blocks + COMBO_BLOCKS, 256>>>(
        src, dst, is_conjugated, edge_is_arom, bond_type, bond_dir, bond_stereo,
        e_conj, e_arom, e_btype, e_bdir, e_bstereo, edge_blocks);

    for (int l = 0; l < LL; l++) {
        // prep: wsplit + zero_stats (+ combo for l>0; layer-0 combo built above)
        int prep_blocks = 2 * WS_BLOCKS + (l > 0 ? COMBO_BLOCKS : 0);
        prep_kernel<<<prep_blocks, 256>>>(
            mlp_w1 + (size_t)l * DD * 2 * DD,
            mlp_w2 + (size_t)l * 2 * DD * DD,
            e_conj    + (size_t)l * 3 * DD,
            e_arom    + (size_t)l * 3 * DD,
            e_btype   + (size_t)l * 23 * DD,
            e_bdir    + (size_t)l * 8 * DD,
            e_bstereo + (size_t)l * 7 * DD);

        aggregate_kernel<<<warp_node_blocks, 256>>>();

        {
            dim3 grid(2, mtiles);
            hsplit_gemm<256, 128, 0><<<grid, 256, GEMM_SMEM>>>(
                aggh, aggl, w1h, w1l,
                mlp_b1 + (size_t)l * 2 * DD, hidh, hidl, nullptr, NN);
        }
        {
            dim3 grid(1, mtiles);
            hsplit_gemm<128, 256, 1><<<grid, 256, GEMM_SMEM>>>(
                hidh, hidl, w2h, w2l,
                mlp_b2 + (size_t)l * DD, nullptr, nullptr, h_ptr, NN);
        }

        float* out = (l == LL - 1) ? (float*)d_out : h_ptr;
        bn_apply_kernel<<<(NN * DD / 4 + 255) / 256, 256>>>(
            bn_gamma + (size_t)l * DD, bn_beta + (size_t)l * DD,
            h_ptr, out, (l < LL - 1) ? 1 : 0);
    }
}

// round 15
// speedup vs baseline: 95.1457x; 1.6735x over previous
#include <cuda_runtime.h>
#include <cuda_bf16.h>
#include <math.h>
#include <cstdint>

#define NN 100000
#define EE 600000
#define DD 128
#define LL 5
#define BN_EPS 1e-5f
#define COMBO 7392
#define NCHUNK ((NN + 1023) / 1024)

// ---------------- device scratch ----------------
__device__ float  g_h[(size_t)NN * DD];                 // raw (pre-BN) layer output
__device__ __nv_bfloat16 g_agg_h[(size_t)NN * DD];
__device__ __nv_bfloat16 g_agg_l[(size_t)NN * DD];
__device__ __nv_bfloat16 g_hid_h[(size_t)NN * 2 * DD];
__device__ __nv_bfloat16 g_hid_l[(size_t)NN * 2 * DD];
__device__ __nv_bfloat16 g_w1h[DD * 2 * DD];
__device__ __nv_bfloat16 g_w1l[DD * 2 * DD];
__device__ __nv_bfloat16 g_w2h[2 * DD * DD];
__device__ __nv_bfloat16 g_w2l[2 * DD * DD];
__device__ float  g_combo[(size_t)COMBO * DD];
__device__ int    g_offs[NN + 1];
__device__ int    g_cursor[NN];
__device__ int    g_chunksums[NCHUNK];
__device__ int2   g_edge_data[EE];
__device__ double g_sum[DD];
__device__ double g_sumsq[DD];
__device__ float  g_scale[DD];
__device__ float  g_shift[DD];

static __device__ __forceinline__ float4 ld4(const float* p) {
    return *reinterpret_cast<const float4*>(p);
}
static __device__ __forceinline__ void add4(float4& a, const float4 b) {
    a.x += b.x; a.y += b.y; a.z += b.z; a.w += b.w;
}

// ================= MMA helpers =================
static __device__ __forceinline__ uint32_t smem_u32(const void* p) {
    uint32_t a;
    asm("{ .reg .u64 t; cvta.to.shared.u64 t, %1; cvt.u32.u64 %0, t; }" : "=r"(a) : "l"(p));
    return a;
}
static __device__ __forceinline__ void ldm_x4(uint32_t* r, uint32_t addr) {
    asm volatile("ldmatrix.sync.aligned.m8n8.x4.shared.b16 {%0,%1,%2,%3}, [%4];"
        : "=r"(r[0]), "=r"(r[1]), "=r"(r[2]), "=r"(r[3]) : "r"(addr));
}
static __device__ __forceinline__ void ldm_x4_t(uint32_t* r, uint32_t addr) {
    asm volatile("ldmatrix.sync.aligned.m8n8.x4.trans.shared.b16 {%0,%1,%2,%3}, [%4];"
        : "=r"(r[0]), "=r"(r[1]), "=r"(r[2]), "=r"(r[3]) : "r"(addr));
}
static __device__ __forceinline__ void mma_bf16(float* d, const uint32_t* a, const uint32_t* b) {
    asm volatile(
        "mma.sync.aligned.m16n8k16.row.col.f32.bf16.bf16.f32 "
        "{%0,%1,%2,%3}, {%4,%5,%6,%7}, {%8,%9}, {%0,%1,%2,%3};"
        : "+f"(d[0]), "+f"(d[1]), "+f"(d[2]), "+f"(d[3])
        : "r"(a[0]), "r"(a[1]), "r"(a[2]), "r"(a[3]), "r"(b[0]), "r"(b[1]));
}
static __device__ __forceinline__ void cp16(uint32_t dst, const void* src, int sz) {
    asm volatile("cp.async.cg.shared.global [%0], [%1], 16, %2;"
        :: "r"(dst), "l"(src), "r"(sz) : "memory");
}
static __device__ __forceinline__ void cp_commit() {
    asm volatile("cp.async.commit_group;" ::: "memory");
}
template <int Nk>
static __device__ __forceinline__ void cp_wait() {
    asm volatile("cp.async.wait_group %0;" :: "n"(Nk) : "memory");
}

// smem stage layout (bytes): A rows 80B stride, B rows 272B stride. 3 stages.
#define OFF_AH_ 0
#define OFF_AL_ 10240
#define OFF_BH_ 20480
#define OFF_BL_ 29184
#define GS_STAGE 37888
#define GEMM_SMEM (3 * GS_STAGE)

static __device__ __forceinline__ uint32_t pack_hi(float v0, float v1) {
    unsigned short h0 = __bfloat16_as_ushort(__float2bfloat16(v0));
    unsigned short h1 = __bfloat16_as_ushort(__float2bfloat16(v1));
    return (uint32_t)h0 | ((uint32_t)h1 << 16);
}
static __device__ __forceinline__ uint32_t pack_lo(float v0, float v1) {
    float f0 = __bfloat162float(__float2bfloat16(v0));
    float f1 = __bfloat162float(__float2bfloat16(v1));
    unsigned short l0 = __bfloat16_as_ushort(__float2bfloat16(v0 - f0));
    unsigned short l1 = __bfloat16_as_ushort(__float2bfloat16(v1 - f1));
    return (uint32_t)l0 | ((uint32_t)l1 << 16);
}

// MODE 0: relu, write bf16 hi/lo (Oh/Ol). MODE 1: no relu, write fp32 Of + column stats.
template <int N, int K, int MODE>
__global__ __launch_bounds__(256, 2) void hsplit_gemm(
    const __nv_bfloat16* __restrict__ Ah, const __nv_bfloat16* __restrict__ Al,
    const __nv_bfloat16* __restrict__ Bh, const __nv_bfloat16* __restrict__ Bl,
    const float* __restrict__ bias,
    __nv_bfloat16* __restrict__ Oh, __nv_bfloat16* __restrict__ Ol,
    float* __restrict__ Of, int M)
{
    extern __shared__ char smem[];
    const uint32_t sb = smem_u32(smem);
    const int tid = threadIdx.x;
    const int lane = tid & 31;
    const int w = tid >> 5;
    const int wm = w & 3;
    const int wn = w >> 2;
    const int bm = blockIdx.y * 128;
    const int bn = blockIdx.x * 128;
    const int NCH = K / 32;

    float acc[2][8][4];
#pragma unroll
    for (int mt = 0; mt < 2; mt++)
#pragma unroll
        for (int nt = 0; nt < 8; nt++)
#pragma unroll
            for (int j = 0; j < 4; j++) acc[mt][nt][j] = 0.f;

    auto fill = [&](int c, int stg) {
        const uint32_t s = sb + stg * GS_STAGE;
        const int k0 = c * 32;
#pragma unroll
        for (int i = 0; i < 2; i++) {
            int ch = tid + i * 256;
            int row = ch >> 2, part = ch & 3;
            int gm = bm + row;
            int sz = (gm < M) ? 16 : 0;
            int gmc = (gm < M) ? gm : 0;
            size_t go = (size_t)gmc * K + k0 + part * 8;
            cp16(s + OFF_AH_ + row * 80 + part * 16, Ah + go, sz);
            cp16(s + OFF_AL_ + row * 80 + part * 16, Al + go, sz);
        }
#pragma unroll
        for (int i = 0; i < 2; i++) {
            int ch = tid + i * 256;
            int kk = ch >> 4, nc = ch & 15;
            size_t go = (size_t)(k0 + kk) * N + bn + nc * 8;
            cp16(s + OFF_BH_ + kk * 272 + nc * 16, Bh + go, 16);
            cp16(s + OFF_BL_ + kk * 272 + nc * 16, Bl + go, 16);
        }
    };

    auto compute = [&](int stg) {
        const uint32_t base = sb + stg * GS_STAGE;
#pragma unroll
        for (int ks = 0; ks < 2; ks++) {
            uint32_t a_hi[2][4], a_lo[2][4];
            int arow = wm * 32 + (lane & 7) + ((lane >> 3) & 1) * 8;
            int acol = ks * 16 + (lane >> 4) * 8;
#pragma unroll
            for (int mt = 0; mt < 2; mt++) {
                uint32_t ao = (uint32_t)((arow + mt * 16) * 80 + acol * 2);
                ldm_x4(a_hi[mt], base + OFF_AH_ + ao);
                ldm_x4(a_lo[mt], base + OFF_AL_ + ao);
            }
            int krow = ks * 16 + (lane & 7) + ((lane >> 3) & 1) * 8;
#pragma unroll
            for (int g = 0; g < 4; g++) {
                int ncol = wn * 64 + g * 16 + (lane >> 4) * 8;
                uint32_t bo = (uint32_t)(krow * 272 + ncol * 2);
                uint32_t th[4], tl[4];
                ldm_x4_t(th, base + OFF_BH_ + bo);
                ldm_x4_t(tl, base + OFF_BL_ + bo);
#pragma unroll
                for (int mt = 0; mt < 2; mt++) {
                    mma_bf16(acc[mt][2 * g],     a_hi[mt], th);
                    mma_bf16(acc[mt][2 * g],     a_hi[mt], tl);
                    mma_bf16(acc[mt][2 * g],     a_lo[mt], th);
                    mma_bf16(acc[mt][2 * g + 1], a_hi[mt], th + 2);
                    mma_bf16(acc[mt][2 * g + 1], a_hi[mt], tl + 2);
                    mma_bf16(acc[mt][2 * g + 1], a_lo[mt], th + 2);
                }
            }
        }
    };

    // ---- 3-stage pipeline, one sync per chunk ----
    fill(0, 0);
    cp_commit();
    if (NCH > 1) { fill(1, 1); cp_commit(); }
    for (int c = 0; c < NCH; c++) {
        if (c + 1 < NCH) cp_wait<1>(); else cp_wait<0>();
        __syncthreads();
        compute(c % 3);
        if (c + 2 < NCH) { fill(c + 2, (c + 2) % 3); cp_commit(); }
    }

    // ---- epilogue (stats buffer reuses stage-0 smem) ----
    float* ssum = (float*)(smem);
    float* ssq  = (float*)(smem + 512);
    if (MODE == 1) {
        __syncthreads();
        if (tid < 128) { ssum[tid] = 0.f; ssq[tid] = 0.f; }
        __syncthreads();
    }
    if (MODE == 0) {
#pragma unroll
        for (int mt = 0; mt < 2; mt++) {
            int row = bm + wm * 32 + mt * 16 + (lane >> 2);
#pragma unroll
            for (int nt = 0; nt < 8; nt++) {
                int col = bn + wn * 64 + nt * 8 + (lane & 3) * 2;
                float b0 = bias[col], b1 = bias[col + 1];
                float v00 = fmaxf(acc[mt][nt][0] + b0, 0.f);
                float v01 = fmaxf(acc[mt][nt][1] + b1, 0.f);
                float v10 = fmaxf(acc[mt][nt][2] + b0, 0.f);
                float v11 = fmaxf(acc[mt][nt][3] + b1, 0.f);
                if (row < M) {
                    *(uint32_t*)(Oh + (size_t)row * N + col) = pack_hi(v00, v01);
                    *(uint32_t*)(Ol + (size_t)row * N + col) = pack_lo(v00, v01);
                }
                if (row + 8 < M) {
                    *(uint32_t*)(Oh + (size_t)(row + 8) * N + col) = pack_hi(v10, v11);
                    *(uint32_t*)(Ol + (size_t)(row + 8) * N + col) = pack_lo(v10, v11);
                }
            }
        }
    } else {
        // register-reduce stats across the 4 row contributions per column,
        // then one atomicAdd per (column, sum/sq): 32 atomics/thread vs 128.
#pragma unroll
        for (int nt = 0; nt < 8; nt++) {
            int col = bn + wn * 64 + nt * 8 + (lane & 3) * 2;
            float b0 = bias[col], b1 = bias[col + 1];
            float s0 = 0.f, s1 = 0.f, q0 = 0.f, q1 = 0.f;
#pragma unroll
            for (int mt = 0; mt < 2; mt++) {
                int row = bm + wm * 32 + mt * 16 + (lane >> 2);
                float v00 = acc[mt][nt][0] + b0, v01 = acc[mt][nt][1] + b1;
                float v10 = acc[mt][nt][2] + b0, v11 = acc[mt][nt][3] + b1;
                if (row < M) {
                    *(float2*)(Of + (size_t)row * N + col) = make_float2(v00, v01);
                    s0 += v00; s1 += v01;
                    q0 += v00 * v00; q1 += v01 * v01;
                }
                if (row + 8 < M) {
                    *(float2*)(Of + (size_t)(row + 8) * N + col) = make_float2(v10, v11);
                    s0 += v10; s1 += v11;
                    q0 += v10 * v10; q1 += v11 * v11;
                }
            }
            int lc = col - bn;
            atomicAdd(&ssum[lc], s0);     atomicAdd(&ssum[lc + 1], s1);
            atomicAdd(&ssq[lc], q0);      atomicAdd(&ssq[lc + 1], q1);
        }
        __syncthreads();
        if (tid < 128) {
            atomicAdd(&g_sum[tid], (double)ssum[tid]);
            atomicAdd(&g_sumsq[tid], (double)ssq[tid]);
        }
    }
}

// ---------------- W split ----------------
__global__ void wsplit_kernel(const float* __restrict__ w,
                              __nv_bfloat16* __restrict__ wh,
                              __nv_bfloat16* __restrict__ wl, int n)
{
    int i = blockIdx.x * blockDim.x + threadIdx.x;
    if (i >= n) return;
    float x = w[i];
    __nv_bfloat16 h = __float2bfloat16(x);
    wh[i] = h;
    wl[i] = __float2bfloat16(x - __bfloat162float(h));
}

// ---------------- seed (+ zero degree counters) ----------------
__global__ void seed_kernel(
    const int* __restrict__ an, const int* __restrict__ fc, const int* __restrict__ ct,
    const int* __restrict__ hy, const int* __restrict__ nh, const int* __restrict__ ar,
    const float* __restrict__ Ean, const float* __restrict__ Efc, const float* __restrict__ Ect,
    const float* __restrict__ Ehy, const float* __restrict__ Enh, const float* __restrict__ Ear)
{
    int gt = blockIdx.x * blockDim.x + threadIdx.x;
    if (gt < NN) g_cursor[gt] = 0;
    int w = gt >> 5;
    if (w >= NN) return;
    int d = (threadIdx.x & 31) * 4;
    float4 v = ld4(Ean + (size_t)an[w] * DD + d);
    add4(v, ld4(Efc + (size_t)fc[w] * DD + d));
    add4(v, ld4(Ect + (size_t)ct[w] * DD + d));
    add4(v, ld4(Ehy + (size_t)hy[w] * DD + d));
    add4(v, ld4(Enh + (size_t)nh[w] * DD + d));
    add4(v, ld4(Ear + (size_t)ar[w] * DD + d));
    *reinterpret_cast<float4*>(g_h + (size_t)w * DD + d) = v;
}

// ---------------- CSR build ----------------
__global__ void deg_count_kernel(const int* __restrict__ dst) {
    int e = blockIdx.x * blockDim.x + threadIdx.x;
    if (e < EE) atomicAdd(&g_cursor[dst[e]], 1);
}
__global__ void scan_chunks_kernel() {
    __shared__ int s[1024];
    int i = blockIdx.x * 1024 + threadIdx.x;
    int v = (i < NN) ? g_cursor[i] : 0;
    s[threadIdx.x] = v;
    __syncthreads();
#pragma unroll
    for (int off = 1; off < 1024; off <<= 1) {
        int x = (threadIdx.x >= off) ? s[threadIdx.x - off] : 0;
        __syncthreads();
        s[threadIdx.x] += x;
        __syncthreads();
    }
    if (i < NN) g_offs[i] = s[threadIdx.x] - v;
    if (threadIdx.x == 1023) g_chunksums[blockIdx.x] = s[1023];
}
__global__ void scan_apply_kernel() {
    __shared__ int base_s;
    if (threadIdx.x == 0) {
        int myChunk = (blockIdx.x * 256) >> 10;
        int b = 0;
        for (int i = 0; i < myChunk; i++) b += g_chunksums[i];
        base_s = b;
    }
    __syncthreads();
    int i = blockIdx.x * 256 + threadIdx.x;
    if (i < NN) {
        int o = g_offs[i] + base_s;
        g_offs[i] = o;
        g_cursor[i] = o;
    }
    if (i == 0) g_offs[NN] = EE;
}

static __device__ __forceinline__ void combo_row(
    int w, int d,
    const float* __restrict__ ec, const float* __restrict__ ea,
    const float* __restrict__ eb, const float* __restrict__ ed,
    const float* __restrict__ es, float* __restrict__ out)
{
    int c = w;
    int vbs = c % 6; c /= 6;
    int vbd = c % 7; c /= 7;
    int vbt = c % 22; c /= 22;
    int via = c & 1;
    int vic = c >> 1;
    float4 v = ld4(ec + (size_t)vic * DD + d);
    add4(v, ld4(ea + (size_t)via * DD + d));
    add4(v, ld4(eb + (size_t)vbt * DD + d));
    add4(v, ld4(ed + (size_t)vbd * DD + d));
    add4(v, ld4(es + (size_t)vbs * DD + d));
    *reinterpret_cast<float4*>(out + (size_t)w * DD + d) = v;
}

// csr_fill + layer-0 combo table, fused (disjoint block ranges)
__global__ void csr_fill_combo_kernel(
    const int* __restrict__ src, const int* __restrict__ dst,
    const int* __restrict__ ic, const int* __restrict__ ia,
    const int* __restrict__ bt, const int* __restrict__ bd,
    const int* __restrict__ bs,
    const float* __restrict__ ec, const float* __restrict__ ea,
    const float* __restrict__ eb, const float* __restrict__ ed,
    const float* __restrict__ es, int edge_blocks)
{
    if ((int)blockIdx.x < edge_blocks) {
        int e = blockIdx.x * 256 + threadIdx.x;
        if (e >= EE) return;
        int pos = atomicAdd(&g_cursor[dst[e]], 1);
        int c = (((ic[e] * 2 + ia[e]) * 22 + bt[e]) * 7 + bd[e]) * 6 + bs[e];
        g_edge_data[pos] = make_int2(src[e], c);
    } else {
        int w = ((blockIdx.x - edge_blocks) * 256 + threadIdx.x) >> 5;
        if (w >= COMBO) return;
        combo_row(w, (threadIdx.x & 31) * 4, ec, ea, eb, ed, es, g_combo);
    }
}

// per-layer combo table (layers >= 1)
__global__ void combo_build_kernel(
    const float* __restrict__ ec, const float* __restrict__ ea,
    const float* __restrict__ eb, const float* __restrict__ ed,
    const float* __restrict__ es)
{
    int w = (blockIdx.x * blockDim.x + threadIdx.x) >> 5;
    if (w >= COMBO) return;
    combo_row(w, (threadIdx.x & 31) * 4, ec, ea, eb, ed, es, g_combo);
}

// ---------------- aggregation: gather + bf16 split output ----------------
__global__ void aggregate_kernel() {
    int w = (blockIdx.x * blockDim.x + threadIdx.x) >> 5;
    if (w >= NN) return;
    int d = (threadIdx.x & 31) * 4;
    float4 v = ld4(g_h + (size_t)w * DD + d);
    add4(v, ld4(g_combo + d));
    int beg = g_offs[w], end = g_offs[w + 1];
    for (int i = beg; i < end; i++) {
        int2 ed = g_edge_data[i];
        add4(v, ld4(g_h + (size_t)ed.x * DD + d));
        add4(v, ld4(g_combo + (size_t)ed.y * DD + d));
    }
    uint2 hi, lo;
    hi.x = pack_hi(v.x, v.y); hi.y = pack_hi(v.z, v.w);
    lo.x = pack_lo(v.x, v.y); lo.y = pack_lo(v.z, v.w);
    *(uint2*)(g_agg_h + (size_t)w * DD + d) = hi;
    *(uint2*)(g_agg_l + (size_t)w * DD + d) = lo;
}

// ---------------- batch norm ----------------
__global__ void zero_stats_kernel() {
    int d = threadIdx.x;
    if (d < DD) { g_sum[d] = 0.0; g_sumsq[d] = 0.0; }
}
__global__ void bn_finalize_kernel(
    const float* __restrict__ gamma, const float* __restrict__ beta)
{
    int d = threadIdx.x;
    if (d < DD) {
        double m = g_sum[d] / (double)NN;
        double var = g_sumsq[d] / (double)NN - m * m;
        float sc = gamma[d] * rsqrtf((float)var + BN_EPS);
        g_scale[d] = sc;
        g_shift[d] = beta[d] - sc * (float)m;
    }
}
__global__ void bn_apply_kernel(
    const float* __restrict__ x, float* __restrict__ out, int relu)
{
    int i = blockIdx.x * blockDim.x + threadIdx.x;
    if (i >= NN * DD / 4) return;
    int d = (i & (DD / 4 - 1)) * 4;
    float4 v = ld4(x + (size_t)i * 4);
    float4 sc = ld4(g_scale + d);
    float4 sh = ld4(g_shift + d);
    v.x = fmaf(sc.x, v.x, sh.x);
    v.y = fmaf(sc.y, v.y, sh.y);
    v.z = fmaf(sc.z, v.z, sh.z);
    v.w = fmaf(sc.w, v.w, sh.w);
    if (relu) {
        v.x = fmaxf(v.x, 0.f); v.y = fmaxf(v.y, 0.f);
        v.z = fmaxf(v.z, 0.f); v.w = fmaxf(v.w, 0.f);
    }
    *reinterpret_cast<float4*>(out + (size_t)i * 4) = v;
}

// ---------------- host launcher ----------------
extern "C" void kernel_launch(void* const* d_in, const int* in_sizes, int n_in,
                              void* d_out, int out_size)
{
    const int* atomic_num      = (const int*)d_in[0];
    const int* formal_charge   = (const int*)d_in[1];
    const int* chiral_tag      = (const int*)d_in[2];
    const int* hybridization   = (const int*)d_in[3];
    const int* num_explicit_hs = (const int*)d_in[4];
    const int* is_aromatic     = (const int*)d_in[5];
    const int* edge_index      = (const int*)d_in[6];
    const int* is_conjugated   = (const int*)d_in[7];
    const int* edge_is_arom    = (const int*)d_in[8];
    const int* bond_type       = (const int*)d_in[9];
    const int* bond_dir        = (const int*)d_in[10];
    const int* bond_stereo     = (const int*)d_in[11];
    const float* emb_atomic_num      = (const float*)d_in[12];
    const float* emb_formal_charge   = (const float*)d_in[13];
    const float* emb_chiral_tag      = (const float*)d_in[14];
    const float* emb_hybridization   = (const float*)d_in[15];
    const float* emb_num_explicit_hs = (const float*)d_in[16];
    const float* emb_is_aromatic     = (const float*)d_in[17];
    const float* e_conj    = (const float*)d_in[18];
    const float* e_arom    = (const float*)d_in[19];
    const float* e_btype   = (const float*)d_in[20];
    const float* e_bdir    = (const float*)d_in[21];
    const float* e_bstereo = (const float*)d_in[22];
    const float* mlp_w1 = (const float*)d_in[23];
    const float* mlp_b1 = (const float*)d_in[24];
    const float* mlp_w2 = (const float*)d_in[25];
    const float* mlp_b2 = (const float*)d_in[26];
    const float* bn_gamma = (const float*)d_in[27];
    const float* bn_beta  = (const float*)d_in[28];

    const int* src = edge_index;
    const int* dst = edge_index + EE;

    float* h_ptr; cudaGetSymbolAddress((void**)&h_ptr, g_h);
    __nv_bfloat16 *aggh, *aggl, *hidh, *hidl, *w1h, *w1l, *w2h, *w2l;
    cudaGetSymbolAddress((void**)&aggh, g_agg_h);
    cudaGetSymbolAddress((void**)&aggl, g_agg_l);
    cudaGetSymbolAddress((void**)&hidh, g_hid_h);
    cudaGetSymbolAddress((void**)&hidl, g_hid_l);
    cudaGetSymbolAddress((void**)&w1h, g_w1h);
    cudaGetSymbolAddress((void**)&w1l, g_w1l);
    cudaGetSymbolAddress((void**)&w2h, g_w2h);
    cudaGetSymbolAddress((void**)&w2l, g_w2l);

    cudaFuncSetAttribute(hsplit_gemm<256, 128, 0>,
                         cudaFuncAttributeMaxDynamicSharedMemorySize, GEMM_SMEM);
    cudaFuncSetAttribute(hsplit_gemm<128, 256, 1>,
                         cudaFuncAttributeMaxDynamicSharedMemorySize, GEMM_SMEM);

    const int warp_node_blocks  = (NN * 32 + 255) / 256;
    const int warp_combo_blocks = (COMBO * 32 + 255) / 256;
    const int edge_blocks = (EE + 255) / 256;
    const int node_blocks = (NN + 255) / 256;
    const int mtiles = (NN + 127) / 128;

    seed_kernel<<<warp_node_blocks, 256>>>(
        atomic_num, formal_charge, chiral_tag, hybridization,
        num_explicit_hs, is_aromatic,
        emb_atomic_num, emb_formal_charge, emb_chiral_tag,
        emb_hybridization, emb_num_explicit_hs, emb_is_aromatic);

    deg_count_kernel<<<edge_blocks, 256>>>(dst);
    scan_chunks_kernel<<<NCHUNK, 1024>>>();
    scan_apply_kernel<<<node_blocks, 256>>>();
    csr_fill_combo_kernel<<<edge_blocks + warp_combo_blocks, 256>>>(
        src, dst, is_conjugated, edge_is_arom, bond_type, bond_dir, bond_stereo,
        e_conj, e_arom, e_btype, e_bdir, e_bstereo, edge_blocks);

    for (int l = 0; l < LL; l++) {
        if (l > 0) {
            combo_build_kernel<<<warp_combo_blocks, 256>>>(
                e_conj    + (size_t)l * 3 * DD,
                e_arom    + (size_t)l * 3 * DD,
                e_btype   + (size_t)l * 23 * DD,
                e_bdir    + (size_t)l * 8 * DD,
                e_bstereo + (size_t)l * 7 * DD);
        }

        aggregate_kernel<<<warp_node_blocks, 256>>>();

        wsplit_kernel<<<(DD * 2 * DD + 255) / 256, 256>>>(
            mlp_w1 + (size_t)l * DD * 2 * DD, w1h, w1l, DD * 2 * DD);
        wsplit_kernel<<<(2 * DD * DD + 255) / 256, 256>>>(
            mlp_w2 + (size_t)l * 2 * DD * DD, w2h, w2l, 2 * DD * DD);

        {
            dim3 grid(2, mtiles);
            hsplit_gemm<256, 128, 0><<<grid, 256, GEMM_SMEM>>>(
                aggh, aggl, w1h, w1l,
                mlp_b1 + (size_t)l * 2 * DD, hidh, hidl, nullptr, NN);
        }
        zero_stats_kernel<<<1, 128>>>();
        {
            dim3 grid(1, mtiles);
            hsplit_gemm<128, 256, 1><<<grid, 256, GEMM_SMEM>>>(
                hidh, hidl, w2h, w2l,
                mlp_b2 + (size_t)l * DD, nullptr, nullptr, h_ptr, NN);
        }

        bn_finalize_kernel<<<1, 128>>>(
            bn_gamma + (size_t)l * DD, bn_beta + (size_t)l * DD);

        float* out = (l == LL - 1) ? (float*)d_out : h_ptr;
        bn_apply_kernel<<<(NN * DD / 4 + 255) / 256, 256>>>(
            h_ptr, out, (l < LL - 1) ? 1 : 0);
    }
}

// round 16
// speedup vs baseline: 113.8705x; 1.1968x over previous
#include <cuda_runtime.h>
#include <cuda_bf16.h>
#include <math.h>
#include <cstdint>

#define NN 100000
#define EE 600000
#define DD 128
#define LL 5
#define BN_EPS 1e-5f
#define COMBO 7392
#define NCHUNK ((NN + 1023) / 1024)

// ---------------- device scratch ----------------
__device__ float  g_h[(size_t)NN * DD];                 // raw (pre-BN) layer output
__device__ __nv_bfloat16 g_agg_h[(size_t)NN * DD];
__device__ __nv_bfloat16 g_agg_l[(size_t)NN * DD];
__device__ __nv_bfloat16 g_hid_h[(size_t)NN * 2 * DD];
__device__ __nv_bfloat16 g_hid_l[(size_t)NN * 2 * DD];
__device__ __nv_bfloat16 g_w1h[DD * 2 * DD];
__device__ __nv_bfloat16 g_w1l[DD * 2 * DD];
__device__ __nv_bfloat16 g_w2h[2 * DD * DD];
__device__ __nv_bfloat16 g_w2l[2 * DD * DD];
__device__ float  g_combo[(size_t)COMBO * DD];
__device__ int    g_offs[NN + 1];
__device__ int    g_cursor[NN];
__device__ int    g_chunksums[NCHUNK];
__device__ int2   g_edge_data[EE];
__device__ double g_sum[DD];
__device__ double g_sumsq[DD];
__device__ float  g_scale[DD];
__device__ float  g_shift[DD];

static __device__ __forceinline__ float4 ld4(const float* p) {
    return *reinterpret_cast<const float4*>(p);
}
static __device__ __forceinline__ void add4(float4& a, const float4 b) {
    a.x += b.x; a.y += b.y; a.z += b.z; a.w += b.w;
}

// ================= MMA helpers =================
static __device__ __forceinline__ uint32_t smem_u32(const void* p) {
    uint32_t a;
    asm("{ .reg .u64 t; cvta.to.shared.u64 t, %1; cvt.u32.u64 %0, t; }" : "=r"(a) : "l"(p));
    return a;
}
static __device__ __forceinline__ void ldm_x4(uint32_t* r, uint32_t addr) {
    asm volatile("ldmatrix.sync.aligned.m8n8.x4.shared.b16 {%0,%1,%2,%3}, [%4];"
        : "=r"(r[0]), "=r"(r[1]), "=r"(r[2]), "=r"(r[3]) : "r"(addr));
}
static __device__ __forceinline__ void ldm_x4_t(uint32_t* r, uint32_t addr) {
    asm volatile("ldmatrix.sync.aligned.m8n8.x4.trans.shared.b16 {%0,%1,%2,%3}, [%4];"
        : "=r"(r[0]), "=r"(r[1]), "=r"(r[2]), "=r"(r[3]) : "r"(addr));
}
static __device__ __forceinline__ void mma_bf16(float* d, const uint32_t* a, const uint32_t* b) {
    asm volatile(
        "mma.sync.aligned.m16n8k16.row.col.f32.bf16.bf16.f32 "
        "{%0,%1,%2,%3}, {%4,%5,%6,%7}, {%8,%9}, {%0,%1,%2,%3};"
        : "+f"(d[0]), "+f"(d[1]), "+f"(d[2]), "+f"(d[3])
        : "r"(a[0]), "r"(a[1]), "r"(a[2]), "r"(a[3]), "r"(b[0]), "r"(b[1]));
}
static __device__ __forceinline__ void cp16(uint32_t dst, const void* src, int sz) {
    asm volatile("cp.async.cg.shared.global [%0], [%1], 16, %2;"
        :: "r"(dst), "l"(src), "r"(sz) : "memory");
}
static __device__ __forceinline__ void cp_commit() {
    asm volatile("cp.async.commit_group;" ::: "memory");
}
template <int Nk>
static __device__ __forceinline__ void cp_wait() {
    asm volatile("cp.async.wait_group %0;" :: "n"(Nk) : "memory");
}

// smem stage layout (bytes): A rows 80B stride, B rows 272B stride. 3 stages.
#define OFF_AH_ 0
#define OFF_AL_ 10240
#define OFF_BH_ 20480
#define OFF_BL_ 29184
#define GS_STAGE 37888
#define GEMM_SMEM (3 * GS_STAGE)

static __device__ __forceinline__ uint32_t pack_hi(float v0, float v1) {
    unsigned short h0 = __bfloat16_as_ushort(__float2bfloat16(v0));
    unsigned short h1 = __bfloat16_as_ushort(__float2bfloat16(v1));
    return (uint32_t)h0 | ((uint32_t)h1 << 16);
}
static __device__ __forceinline__ uint32_t pack_lo(float v0, float v1) {
    float f0 = __bfloat162float(__float2bfloat16(v0));
    float f1 = __bfloat162float(__float2bfloat16(v1));
    unsigned short l0 = __bfloat16_as_ushort(__float2bfloat16(v0 - f0));
    unsigned short l1 = __bfloat16_as_ushort(__float2bfloat16(v1 - f1));
    return (uint32_t)l0 | ((uint32_t)l1 << 16);
}

// MODE 0: relu, write bf16 hi/lo (Oh/Ol). MODE 1: no relu, write fp32 Of + column stats.
template <int N, int K, int MODE>
__global__ __launch_bounds__(256, 2) void hsplit_gemm(
    const __nv_bfloat16* __restrict__ Ah, const __nv_bfloat16* __restrict__ Al,
    const __nv_bfloat16* __restrict__ Bh, const __nv_bfloat16* __restrict__ Bl,
    const float* __restrict__ bias,
    __nv_bfloat16* __restrict__ Oh, __nv_bfloat16* __restrict__ Ol,
    float* __restrict__ Of, int M)
{
    extern __shared__ char smem[];
    const uint32_t sb = smem_u32(smem);
    const int tid = threadIdx.x;
    const int lane = tid & 31;
    const int w = tid >> 5;
    const int wm = w & 3;
    const int wn = w >> 2;
    const int bm = blockIdx.y * 128;
    const int bn = blockIdx.x * 128;
    const int NCH = K / 32;

    float acc[2][8][4];
#pragma unroll
    for (int mt = 0; mt < 2; mt++)
#pragma unroll
        for (int nt = 0; nt < 8; nt++)
#pragma unroll
            for (int j = 0; j < 4; j++) acc[mt][nt][j] = 0.f;

    auto fill = [&](int c, int stg) {
        const uint32_t s = sb + stg * GS_STAGE;
        const int k0 = c * 32;
#pragma unroll
        for (int i = 0; i < 2; i++) {
            int ch = tid + i * 256;
            int row = ch >> 2, part = ch & 3;
            int gm = bm + row;
            int sz = (gm < M) ? 16 : 0;
            int gmc = (gm < M) ? gm : 0;
            size_t go = (size_t)gmc * K + k0 + part * 8;
            cp16(s + OFF_AH_ + row * 80 + part * 16, Ah + go, sz);
            cp16(s + OFF_AL_ + row * 80 + part * 16, Al + go, sz);
        }
#pragma unroll
        for (int i = 0; i < 2; i++) {
            int ch = tid + i * 256;
            int kk = ch >> 4, nc = ch & 15;
            size_t go = (size_t)(k0 + kk) * N + bn + nc * 8;
            cp16(s + OFF_BH_ + kk * 272 + nc * 16, Bh + go, 16);
            cp16(s + OFF_BL_ + kk * 272 + nc * 16, Bl + go, 16);
        }
    };

    auto compute = [&](int stg) {
        const uint32_t base = sb + stg * GS_STAGE;
#pragma unroll
        for (int ks = 0; ks < 2; ks++) {
            uint32_t a_hi[2][4], a_lo[2][4];
            int arow = wm * 32 + (lane & 7) + ((lane >> 3) & 1) * 8;
            int acol = ks * 16 + (lane >> 4) * 8;
#pragma unroll
            for (int mt = 0; mt < 2; mt++) {
                uint32_t ao = (uint32_t)((arow + mt * 16) * 80 + acol * 2);
                ldm_x4(a_hi[mt], base + OFF_AH_ + ao);
                ldm_x4(a_lo[mt], base + OFF_AL_ + ao);
            }
            int krow = ks * 16 + (lane & 7) + ((lane >> 3) & 1) * 8;
#pragma unroll
            for (int g = 0; g < 4; g++) {
                int ncol = wn * 64 + g * 16 + (lane >> 4) * 8;
                uint32_t bo = (uint32_t)(krow * 272 + ncol * 2);
                uint32_t th[4], tl[4];
                ldm_x4_t(th, base + OFF_BH_ + bo);
                ldm_x4_t(tl, base + OFF_BL_ + bo);
#pragma unroll
                for (int mt = 0; mt < 2; mt++) {
                    mma_bf16(acc[mt][2 * g],     a_hi[mt], th);
                    mma_bf16(acc[mt][2 * g],     a_hi[mt], tl);
                    mma_bf16(acc[mt][2 * g],     a_lo[mt], th);
                    mma_bf16(acc[mt][2 * g + 1], a_hi[mt], th + 2);
                    mma_bf16(acc[mt][2 * g + 1], a_hi[mt], tl + 2);
                    mma_bf16(acc[mt][2 * g + 1], a_lo[mt], th + 2);
                }
            }
        }
    };

    // ---- 3-stage pipeline, one sync per chunk ----
    fill(0, 0);
    cp_commit();
    if (NCH > 1) { fill(1, 1); cp_commit(); }
    for (int c = 0; c < NCH; c++) {
        if (c + 1 < NCH) cp_wait<1>(); else cp_wait<0>();
        __syncthreads();
        compute(c % 3);
        if (c + 2 < NCH) { fill(c + 2, (c + 2) % 3); cp_commit(); }
    }

    // ---- epilogue (stats buffer reuses stage-0 smem) ----
    float* ssum = (float*)(smem);
    float* ssq  = (float*)(smem + 512);
    if (MODE == 1) {
        __syncthreads();
        if (tid < 128) { ssum[tid] = 0.f; ssq[tid] = 0.f; }
        __syncthreads();
    }
    if (MODE == 0) {
#pragma unroll
        for (int mt = 0; mt < 2; mt++) {
            int row = bm + wm * 32 + mt * 16 + (lane >> 2);
#pragma unroll
            for (int nt = 0; nt < 8; nt++) {
                int col = bn + wn * 64 + nt * 8 + (lane & 3) * 2;
                float b0 = bias[col], b1 = bias[col + 1];
                float v00 = fmaxf(acc[mt][nt][0] + b0, 0.f);
                float v01 = fmaxf(acc[mt][nt][1] + b1, 0.f);
                float v10 = fmaxf(acc[mt][nt][2] + b0, 0.f);
                float v11 = fmaxf(acc[mt][nt][3] + b1, 0.f);
                if (row < M) {
                    *(uint32_t*)(Oh + (size_t)row * N + col) = pack_hi(v00, v01);
                    *(uint32_t*)(Ol + (size_t)row * N + col) = pack_lo(v00, v01);
                }
                if (row + 8 < M) {
                    *(uint32_t*)(Oh + (size_t)(row + 8) * N + col) = pack_hi(v10, v11);
                    *(uint32_t*)(Ol + (size_t)(row + 8) * N + col) = pack_lo(v10, v11);
                }
            }
        }
    } else {
        // register-reduce across the 4 row contributions, then warp-shuffle
        // reduce across the 8 lanes sharing the same column (lane & 3 equal);
        // only lanes 0-3 issue atomics: 4 atomics/thread total.
#pragma unroll
        for (int nt = 0; nt < 8; nt++) {
            int col = bn + wn * 64 + nt * 8 + (lane & 3) * 2;
            float b0 = bias[col], b1 = bias[col + 1];
            float s0 = 0.f, s1 = 0.f, q0 = 0.f, q1 = 0.f;
#pragma unroll
            for (int mt = 0; mt < 2; mt++) {
                int row = bm + wm * 32 + mt * 16 + (lane >> 2);
                float v00 = acc[mt][nt][0] + b0, v01 = acc[mt][nt][1] + b1;
                float v10 = acc[mt][nt][2] + b0, v11 = acc[mt][nt][3] + b1;
                if (row < M) {
                    *(float2*)(Of + (size_t)row * N + col) = make_float2(v00, v01);
                    s0 += v00; s1 += v01;
                    q0 += v00 * v00; q1 += v01 * v01;
                }
                if (row + 8 < M) {
                    *(float2*)(Of + (size_t)(row + 8) * N + col) = make_float2(v10, v11);
                    s0 += v10; s1 += v11;
                    q0 += v10 * v10; q1 += v11 * v11;
                }
            }
#pragma unroll
            for (int delta = 16; delta >= 4; delta >>= 1) {
                s0 += __shfl_down_sync(0xffffffffu, s0, delta);
                s1 += __shfl_down_sync(0xffffffffu, s1, delta);
                q0 += __shfl_down_sync(0xffffffffu, q0, delta);
                q1 += __shfl_down_sync(0xffffffffu, q1, delta);
            }
            if (lane < 4) {
                int lc = col - bn;
                atomicAdd(&ssum[lc], s0);     atomicAdd(&ssum[lc + 1], s1);
                atomicAdd(&ssq[lc], q0);      atomicAdd(&ssq[lc + 1], q1);
            }
        }
        __syncthreads();
        if (tid < 128) {
            atomicAdd(&g_sum[tid], (double)ssum[tid]);
            atomicAdd(&g_sumsq[tid], (double)ssq[tid]);
        }
    }
}

// ---------------- W split ----------------
__global__ void wsplit_kernel(const float* __restrict__ w,
                              __nv_bfloat16* __restrict__ wh,
                              __nv_bfloat16* __restrict__ wl, int n)
{
    int i = blockIdx.x * blockDim.x + threadIdx.x;
    if (i >= n) return;
    float x = w[i];
    __nv_bfloat16 h = __float2bfloat16(x);
    wh[i] = h;
    wl[i] = __float2bfloat16(x - __bfloat162float(h));
}

// ---------------- seed (+ zero degree counters) ----------------
__global__ void seed_kernel(
    const int* __restrict__ an, const int* __restrict__ fc, const int* __restrict__ ct,
    const int* __restrict__ hy, const int* __restrict__ nh, const int* __restrict__ ar,
    const float* __restrict__ Ean, const float* __restrict__ Efc, const float* __restrict__ Ect,
    const float* __restrict__ Ehy, const float* __restrict__ Enh, const float* __restrict__ Ear)
{
    int gt = blockIdx.x * blockDim.x + threadIdx.x;
    if (gt < NN) g_cursor[gt] = 0;
    int w = gt >> 5;
    if (w >= NN) return;
    int d = (threadIdx.x & 31) * 4;
    float4 v = ld4(Ean + (size_t)an[w] * DD + d);
    add4(v, ld4(Efc + (size_t)fc[w] * DD + d));
    add4(v, ld4(Ect + (size_t)ct[w] * DD + d));
    add4(v, ld4(Ehy + (size_t)hy[w] * DD + d));
    add4(v, ld4(Enh + (size_t)nh[w] * DD + d));
    add4(v, ld4(Ear + (size_t)ar[w] * DD + d));
    *reinterpret_cast<float4*>(g_h + (size_t)w * DD + d) = v;
}

// ---------------- CSR build ----------------
__global__ void deg_count_kernel(const int* __restrict__ dst) {
    int e = blockIdx.x * blockDim.x + threadIdx.x;
    if (e < EE) atomicAdd(&g_cursor[dst[e]], 1);
}
__global__ void scan_chunks_kernel() {
    __shared__ int s[1024];
    int i = blockIdx.x * 1024 + threadIdx.x;
    int v = (i < NN) ? g_cursor[i] : 0;
    s[threadIdx.x] = v;
    __syncthreads();
#pragma unroll
    for (int off = 1; off < 1024; off <<= 1) {
        int x = (threadIdx.x >= off) ? s[threadIdx.x - off] : 0;
        __syncthreads();
        s[threadIdx.x] += x;
        __syncthreads();
    }
    if (i < NN) g_offs[i] = s[threadIdx.x] - v;
    if (threadIdx.x == 1023) g_chunksums[blockIdx.x] = s[1023];
}
__global__ void scan_apply_kernel() {
    __shared__ int base_s;
    if (threadIdx.x == 0) {
        int myChunk = (blockIdx.x * 256) >> 10;
        int b = 0;
        for (int i = 0; i < myChunk; i++) b += g_chunksums[i];
        base_s = b;
    }
    __syncthreads();
    int i = blockIdx.x * 256 + threadIdx.x;
    if (i < NN) {
        int o = g_offs[i] + base_s;
        g_offs[i] = o;
        g_cursor[i] = o;
    }
    if (i == 0) g_offs[NN] = EE;
}

static __device__ __forceinline__ void combo_row(
    int w, int d,
    const float* __restrict__ ec, const float* __restrict__ ea,
    const float* __restrict__ eb, const float* __restrict__ ed,
    const float* __restrict__ es, float* __restrict__ out)
{
    int c = w;
    int vbs = c % 6; c /= 6;
    int vbd = c % 7; c /= 7;
    int vbt = c % 22; c /= 22;
    int via = c & 1;
    int vic = c >> 1;
    float4 v = ld4(ec + (size_t)vic * DD + d);
    add4(v, ld4(ea + (size_t)via * DD + d));
    add4(v, ld4(eb + (size_t)vbt * DD + d));
    add4(v, ld4(ed + (size_t)vbd * DD + d));
    add4(v, ld4(es + (size_t)vbs * DD + d));
    *reinterpret_cast<float4*>(out + (size_t)w * DD + d) = v;
}

// csr_fill + layer-0 combo table, fused (disjoint block ranges)
__global__ void csr_fill_combo_kernel(
    const int* __restrict__ src, const int* __restrict__ dst,
    const int* __restrict__ ic, const int* __restrict__ ia,
    const int* __restrict__ bt, const int* __restrict__ bd,
    const int* __restrict__ bs,
    const float* __restrict__ ec, const float* __restrict__ ea,
    const float* __restrict__ eb, const float* __restrict__ ed,
    const float* __restrict__ es, int edge_blocks)
{
    if ((int)blockIdx.x < edge_blocks) {
        int e = blockIdx.x * 256 + threadIdx.x;
        if (e >= EE) return;
        int pos = atomicAdd(&g_cursor[dst[e]], 1);
        int c = (((ic[e] * 2 + ia[e]) * 22 + bt[e]) * 7 + bd[e]) * 6 + bs[e];
        g_edge_data[pos] = make_int2(src[e], c);
    } else {
        int w = ((blockIdx.x - edge_blocks) * 256 + threadIdx.x) >> 5;
        if (w >= COMBO) return;
        combo_row(w, (threadIdx.x & 31) * 4, ec, ea, eb, ed, es, g_combo);
    }
}

// per-layer combo table (layers >= 1)
__global__ void combo_build_kernel(
    const float* __restrict__ ec, const float* __restrict__ ea,
    const float* __restrict__ eb, const float* __restrict__ ed,
    const float* __restrict__ es)
{
    int w = (blockIdx.x * blockDim.x + threadIdx.x) >> 5;
    if (w >= COMBO) return;
    combo_row(w, (threadIdx.x & 31) * 4, ec, ea, eb, ed, es, g_combo);
}

// ---------------- aggregation: gather + bf16 split output ----------------
__global__ void aggregate_kernel() {
    int w = (blockIdx.x * blockDim.x + threadIdx.x) >> 5;
    if (w >= NN) return;
    int d = (threadIdx.x & 31) * 4;
    float4 v = ld4(g_h + (size_t)w * DD + d);
    add4(v, ld4(g_combo + d));
    int beg = g_offs[w], end = g_offs[w + 1];
    for (int i = beg; i < end; i++) {
        int2 ed = g_edge_data[i];
        add4(v, ld4(g_h + (size_t)ed.x * DD + d));
        add4(v, ld4(g_combo + (size_t)ed.y * DD + d));
    }
    uint2 hi, lo;
    hi.x = pack_hi(v.x, v.y); hi.y = pack_hi(v.z, v.w);
    lo.x = pack_lo(v.x, v.y); lo.y = pack_lo(v.z, v.w);
    *(uint2*)(g_agg_h + (size_t)w * DD + d) = hi;
    *(uint2*)(g_agg_l + (size_t)w * DD + d) = lo;
}

// ---------------- batch norm ----------------
__global__ void zero_stats_kernel() {
    int d = threadIdx.x;
    if (d < DD) { g_sum[d] = 0.0; g_sumsq[d] = 0.0; }
}
__global__ void bn_finalize_kernel(
    const float* __restrict__ gamma, const float* __restrict__ beta)
{
    int d = threadIdx.x;
    if (d < DD) {
        double m = g_sum[d] / (double)NN;
        double var = g_sumsq[d] / (double)NN - m * m;
        float sc = gamma[d] * rsqrtf((float)var + BN_EPS);
        g_scale[d] = sc;
        g_shift[d] = beta[d] - sc * (float)m;
    }
}
__global__ void bn_apply_kernel(
    const float* __restrict__ x, float* __restrict__ out, int relu)
{
    int i = blockIdx.x * blockDim.x + threadIdx.x;
    if (i >= NN * DD / 4) return;
    int d = (i & (DD / 4 - 1)) * 4;
    float4 v = ld4(x + (size_t)i * 4);
    float4 sc = ld4(g_scale + d);
    float4 sh = ld4(g_shift + d);
    v.x = fmaf(sc.x, v.x, sh.x);
    v.y = fmaf(sc.y, v.y, sh.y);
    v.z = fmaf(sc.z, v.z, sh.z);
    v.w = fmaf(sc.w, v.w, sh.w);
    if (relu) {
        v.x = fmaxf(v.x, 0.f); v.y = fmaxf(v.y, 0.f);
        v.z = fmaxf(v.z, 0.f); v.w = fmaxf(v.w, 0.f);
    }
    *reinterpret_cast<float4*>(out + (size_t)i * 4) = v;
}

// ---------------- host launcher ----------------
extern "C" void kernel_launch(void* const* d_in, const int* in_sizes, int n_in,
                              void* d_out, int out_size)
{
    const int* atomic_num      = (const int*)d_in[0];
    const int* formal_charge   = (const int*)d_in[1];
    const int* chiral_tag      = (const int*)d_in[2];
    const int* hybridization   = (const int*)d_in[3];
    const int* num_explicit_hs = (const int*)d_in[4];
    const int* is_aromatic     = (const int*)d_in[5];
    const int* edge_index      = (const int*)d_in[6];
    const int* is_conjugated   = (const int*)d_in[7];
    const int* edge_is_arom    = (const int*)d_in[8];
    const int* bond_type       = (const int*)d_in[9];
    const int* bond_dir        = (const int*)d_in[10];
    const int* bond_stereo     = (const int*)d_in[11];
    const float* emb_atomic_num      = (const float*)d_in[12];
    const float* emb_formal_charge   = (const float*)d_in[13];
    const float* emb_chiral_tag      = (const float*)d_in[14];
    const float* emb_hybridization   = (const float*)d_in[15];
    const float* emb_num_explicit_hs = (const float*)d_in[16];
    const float* emb_is_aromatic     = (const float*)d_in[17];
    const float* e_conj    = (const float*)d_in[18];
    const float* e_arom    = (const float*)d_in[19];
    const float* e_btype   = (const float*)d_in[20];
    const float* e_bdir    = (const float*)d_in[21];
    const float* e_bstereo = (const float*)d_in[22];
    const float* mlp_w1 = (const float*)d_in[23];
    const float* mlp_b1 = (const float*)d_in[24];
    const float* mlp_w2 = (const float*)d_in[25];
    const float* mlp_b2 = (const float*)d_in[26];
    const float* bn_gamma = (const float*)d_in[27];
    const float* bn_beta  = (const float*)d_in[28];

    const int* src = edge_index;
    const int* dst = edge_index + EE;

    float* h_ptr; cudaGetSymbolAddress((void**)&h_ptr, g_h);
    __nv_bfloat16 *aggh, *aggl, *hidh, *hidl, *w1h, *w1l, *w2h, *w2l;
    cudaGetSymbolAddress((void**)&aggh, g_agg_h);
    cudaGetSymbolAddress((void**)&aggl, g_agg_l);
    cudaGetSymbolAddress((void**)&hidh, g_hid_h);
    cudaGetSymbolAddress((void**)&hidl, g_hid_l);
    cudaGetSymbolAddress((void**)&w1h, g_w1h);
    cudaGetSymbolAddress((void**)&w1l, g_w1l);
    cudaGetSymbolAddress((void**)&w2h, g_w2h);
    cudaGetSymbolAddress((void**)&w2l, g_w2l);

    cudaFuncSetAttribute(hsplit_gemm<256, 128, 0>,
                         cudaFuncAttributeMaxDynamicSharedMemorySize, GEMM_SMEM);
    cudaFuncSetAttribute(hsplit_gemm<128, 256, 1>,
                         cudaFuncAttributeMaxDynamicSharedMemorySize, GEMM_SMEM);

    const int warp_node_blocks  = (NN * 32 + 255) / 256;
    const int warp_combo_blocks = (COMBO * 32 + 255) / 256;
    const int edge_blocks = (EE + 255) / 256;
    const int node_blocks = (NN + 255) / 256;
    const int mtiles = (NN + 127) / 128;

    seed_kernel<<<warp_node_blocks, 256>>>(
        atomic_num, formal_charge, chiral_tag, hybridization,
        num_explicit_hs, is_aromatic,
        emb_atomic_num, emb_formal_charge, emb_chiral_tag,
        emb_hybridization, emb_num_explicit_hs, emb_is_aromatic);

    deg_count_kernel<<<edge_blocks, 256>>>(dst);
    scan_chunks_kernel<<<NCHUNK, 1024>>>();
    scan_apply_kernel<<<node_blocks, 256>>>();
    csr_fill_combo_kernel<<<edge_blocks + warp_combo_blocks, 256>>>(
        src, dst, is_conjugated, edge_is_arom, bond_type, bond_dir, bond_stereo,
        e_conj, e_arom, e_btype, e_bdir, e_bstereo, edge_blocks);

    for (int l = 0; l < LL; l++) {
        if (l > 0) {
            combo_build_kernel<<<warp_combo_blocks, 256>>>(
                e_conj    + (size_t)l * 3 * DD,
                e_arom    + (size_t)l * 3 * DD,
                e_btype   + (size_t)l * 23 * DD,
                e_bdir    + (size_t)l * 8 * DD,
                e_bstereo + (size_t)l * 7 * DD);
        }

        aggregate_kernel<<<warp_node_blocks, 256>>>();

        wsplit_kernel<<<(DD * 2 * DD + 255) / 256, 256>>>(
            mlp_w1 + (size_t)l * DD * 2 * DD, w1h, w1l, DD * 2 * DD);
        wsplit_kernel<<<(2 * DD * DD + 255) / 256, 256>>>(
            mlp_w2 + (size_t)l * 2 * DD * DD, w2h, w2l, 2 * DD * DD);

        {
            dim3 grid(2, mtiles);
            hsplit_gemm<256, 128, 0><<<grid, 256, GEMM_SMEM>>>(
                aggh, aggl, w1h, w1l,
                mlp_b1 + (size_t)l * 2 * DD, hidh, hidl, nullptr, NN);
        }
        zero_stats_kernel<<<1, 128>>>();
        {
            dim3 grid(1, mtiles);
            hsplit_gemm<128, 256, 1><<<grid, 256, GEMM_SMEM>>>(
                hidh, hidl, w2h, w2l,
                mlp_b2 + (size_t)l * DD, nullptr, nullptr, h_ptr, NN);
        }

        bn_finalize_kernel<<<1, 128>>>(
            bn_gamma + (size_t)l * DD, bn_beta + (size_t)l * DD);

        float* out = (l == LL - 1) ? (float*)d_out : h_ptr;
        bn_apply_kernel<<<(NN * DD / 4 + 255) / 256, 256>>>(
            h_ptr, out, (l < LL - 1) ? 1 : 0);
    }
}

// round 17
// speedup vs baseline: 116.8813x; 1.0264x over previous
#include <cuda_runtime.h>
#include <cuda_bf16.h>
#include <math.h>
#include <cstdint>

#define NN 100000
#define EE 600000
#define DD 128
#define LL 5
#define BN_EPS 1e-5f
#define COMBO 7392
#define NCHUNK ((NN + 1023) / 1024)
#define COMBO_BLOCKS ((COMBO * 32 + 255) / 256)   // 924
#define WS_BLOCKS 128                              // 32768/256

// ---------------- device scratch ----------------
__device__ float  g_h[(size_t)NN * DD];
__device__ __nv_bfloat16 g_agg_h[(size_t)NN * DD];
__device__ __nv_bfloat16 g_agg_l[(size_t)NN * DD];
__device__ __nv_bfloat16 g_hid_h[(size_t)NN * 2 * DD];
__device__ __nv_bfloat16 g_hid_l[(size_t)NN * 2 * DD];
__device__ __nv_bfloat16 g_w1h[DD * 2 * DD];
__device__ __nv_bfloat16 g_w1l[DD * 2 * DD];
__device__ __nv_bfloat16 g_w2h[2 * DD * DD];
__device__ __nv_bfloat16 g_w2l[2 * DD * DD];
__device__ float  g_combo[(size_t)COMBO * DD];
__device__ int    g_offs[NN + 1];
__device__ int    g_cursor[NN];
__device__ int    g_chunksums[NCHUNK];
__device__ int2   g_edge_data[EE];
__device__ double g_sum[DD];
__device__ double g_sumsq[DD];
__device__ float  g_scale[DD];
__device__ float  g_shift[DD];

static __device__ __forceinline__ float4 ld4(const float* p) {
    return *reinterpret_cast<const float4*>(p);
}
static __device__ __forceinline__ void add4(float4& a, const float4 b) {
    a.x += b.x; a.y += b.y; a.z += b.z; a.w += b.w;
}

// ================= MMA helpers =================
static __device__ __forceinline__ uint32_t smem_u32(const void* p) {
    uint32_t a;
    asm("{ .reg .u64 t; cvta.to.shared.u64 t, %1; cvt.u32.u64 %0, t; }" : "=r"(a) : "l"(p));
    return a;
}
static __device__ __forceinline__ void ldm_x4(uint32_t* r, uint32_t addr) {
    asm volatile("ldmatrix.sync.aligned.m8n8.x4.shared.b16 {%0,%1,%2,%3}, [%4];"
        : "=r"(r[0]), "=r"(r[1]), "=r"(r[2]), "=r"(r[3]) : "r"(addr));
}
static __device__ __forceinline__ void ldm_x4_t(uint32_t* r, uint32_t addr) {
    asm volatile("ldmatrix.sync.aligned.m8n8.x4.trans.shared.b16 {%0,%1,%2,%3}, [%4];"
        : "=r"(r[0]), "=r"(r[1]), "=r"(r[2]), "=r"(r[3]) : "r"(addr));
}
static __device__ __forceinline__ void mma_bf16(float* d, const uint32_t* a, const uint32_t* b) {
    asm volatile(
        "mma.sync.aligned.m16n8k16.row.col.f32.bf16.bf16.f32 "
        "{%0,%1,%2,%3}, {%4,%5,%6,%7}, {%8,%9}, {%0,%1,%2,%3};"
        : "+f"(d[0]), "+f"(d[1]), "+f"(d[2]), "+f"(d[3])
        : "r"(a[0]), "r"(a[1]), "r"(a[2]), "r"(a[3]), "r"(b[0]), "r"(b[1]));
}
static __device__ __forceinline__ void cp16(uint32_t dst, const void* src, int sz) {
    asm volatile("cp.async.cg.shared.global [%0], [%1], 16, %2;"
        :: "r"(dst), "l"(src), "r"(sz) : "memory");
}
static __device__ __forceinline__ void cp_commit() {
    asm volatile("cp.async.commit_group;" ::: "memory");
}
template <int Nk>
static __device__ __forceinline__ void cp_wait() {
    asm volatile("cp.async.wait_group %0;" :: "n"(Nk) : "memory");
}

// smem stage layout (bytes): A rows 80B stride, B rows 272B stride. 3 stages.
#define OFF_AH_ 0
#define OFF_AL_ 10240
#define OFF_BH_ 20480
#define OFF_BL_ 29184
#define GS_STAGE 37888
#define GEMM_SMEM (3 * GS_STAGE)

static __device__ __forceinline__ uint32_t pack_hi(float v0, float v1) {
    unsigned short h0 = __bfloat16_as_ushort(__float2bfloat16(v0));
    unsigned short h1 = __bfloat16_as_ushort(__float2bfloat16(v1));
    return (uint32_t)h0 | ((uint32_t)h1 << 16);
}
static __device__ __forceinline__ uint32_t pack_lo(float v0, float v1) {
    float f0 = __bfloat162float(__float2bfloat16(v0));
    float f1 = __bfloat162float(__float2bfloat16(v1));
    unsigned short l0 = __bfloat16_as_ushort(__float2bfloat16(v0 - f0));
    unsigned short l1 = __bfloat16_as_ushort(__float2bfloat16(v1 - f1));
    return (uint32_t)l0 | ((uint32_t)l1 << 16);
}

// MODE 0: relu, write bf16 hi/lo (Oh/Ol). MODE 1: no relu, write fp32 Of + column stats.
template <int N, int K, int MODE>
__global__ __launch_bounds__(256, 2) void hsplit_gemm(
    const __nv_bfloat16* __restrict__ Ah, const __nv_bfloat16* __restrict__ Al,
    const __nv_bfloat16* __restrict__ Bh, const __nv_bfloat16* __restrict__ Bl,
    const float* __restrict__ bias,
    __nv_bfloat16* __restrict__ Oh, __nv_bfloat16* __restrict__ Ol,
    float* __restrict__ Of, int M)
{
    extern __shared__ char smem[];
    const uint32_t sb = smem_u32(smem);
    const int tid = threadIdx.x;
    const int lane = tid & 31;
    const int w = tid >> 5;
    const int wm = w & 3;
    const int wn = w >> 2;
    const int bm = blockIdx.y * 128;
    const int bn = blockIdx.x * 128;
    const int NCH = K / 32;

    float acc[2][8][4];
#pragma unroll
    for (int mt = 0; mt < 2; mt++)
#pragma unroll
        for (int nt = 0; nt < 8; nt++)
#pragma unroll
            for (int j = 0; j < 4; j++) acc[mt][nt][j] = 0.f;

    auto fill = [&](int c, int stg) {
        const uint32_t s = sb + stg * GS_STAGE;
        const int k0 = c * 32;
#pragma unroll
        for (int i = 0; i < 2; i++) {
            int ch = tid + i * 256;
            int row = ch >> 2, part = ch & 3;
            int gm = bm + row;
            int sz = (gm < M) ? 16 : 0;
            int gmc = (gm < M) ? gm : 0;
            size_t go = (size_t)gmc * K + k0 + part * 8;
            cp16(s + OFF_AH_ + row * 80 + part * 16, Ah + go, sz);
            cp16(s + OFF_AL_ + row * 80 + part * 16, Al + go, sz);
        }
#pragma unroll
        for (int i = 0; i < 2; i++) {
            int ch = tid + i * 256;
            int kk = ch >> 4, nc = ch & 15;
            size_t go = (size_t)(k0 + kk) * N + bn + nc * 8;
            cp16(s + OFF_BH_ + kk * 272 + nc * 16, Bh + go, 16);
            cp16(s + OFF_BL_ + kk * 272 + nc * 16, Bl + go, 16);
        }
    };

    auto compute = [&](int stg) {
        const uint32_t base = sb + stg * GS_STAGE;
#pragma unroll
        for (int ks = 0; ks < 2; ks++) {
            uint32_t a_hi[2][4], a_lo[2][4];
            int arow = wm * 32 + (lane & 7) + ((lane >> 3) & 1) * 8;
            int acol = ks * 16 + (lane >> 4) * 8;
#pragma unroll
            for (int mt = 0; mt < 2; mt++) {
                uint32_t ao = (uint32_t)((arow + mt * 16) * 80 + acol * 2);
                ldm_x4(a_hi[mt], base + OFF_AH_ + ao);
                ldm_x4(a_lo[mt], base + OFF_AL_ + ao);
            }
            int krow = ks * 16 + (lane & 7) + ((lane >> 3) & 1) * 8;
#pragma unroll
            for (int g = 0; g < 4; g++) {
                int ncol = wn * 64 + g * 16 + (lane >> 4) * 8;
                uint32_t bo = (uint32_t)(krow * 272 + ncol * 2);
                uint32_t th[4], tl[4];
                ldm_x4_t(th, base + OFF_BH_ + bo);
                ldm_x4_t(tl, base + OFF_BL_ + bo);
#pragma unroll
                for (int mt = 0; mt < 2; mt++) {
                    mma_bf16(acc[mt][2 * g],     a_hi[mt], th);
                    mma_bf16(acc[mt][2 * g],     a_hi[mt], tl);
                    mma_bf16(acc[mt][2 * g],     a_lo[mt], th);
                    mma_bf16(acc[mt][2 * g + 1], a_hi[mt], th + 2);
                    mma_bf16(acc[mt][2 * g + 1], a_hi[mt], tl + 2);
                    mma_bf16(acc[mt][2 * g + 1], a_lo[mt], th + 2);
                }
            }
        }
    };

    // ---- 3-stage pipeline, one sync per chunk ----
    fill(0, 0);
    cp_commit();
    if (NCH > 1) { fill(1, 1); cp_commit(); }
    for (int c = 0; c < NCH; c++) {
        if (c + 1 < NCH) cp_wait<1>(); else cp_wait<0>();
        __syncthreads();
        compute(c % 3);
        if (c + 2 < NCH) { fill(c + 2, (c + 2) % 3); cp_commit(); }
    }

    // ---- epilogue (stats buffer reuses stage-0 smem) ----
    float* ssum = (float*)(smem);
    float* ssq  = (float*)(smem + 512);
    if (MODE == 1) {
        __syncthreads();
        if (tid < 128) { ssum[tid] = 0.f; ssq[tid] = 0.f; }
        __syncthreads();
    }
    if (MODE == 0) {
#pragma unroll
        for (int mt = 0; mt < 2; mt++) {
            int row = bm + wm * 32 + mt * 16 + (lane >> 2);
#pragma unroll
            for (int nt = 0; nt < 8; nt++) {
                int col = bn + wn * 64 + nt * 8 + (lane & 3) * 2;
                float b0 = bias[col], b1 = bias[col + 1];
                float v00 = fmaxf(acc[mt][nt][0] + b0, 0.f);
                float v01 = fmaxf(acc[mt][nt][1] + b1, 0.f);
                float v10 = fmaxf(acc[mt][nt][2] + b0, 0.f);
                float v11 = fmaxf(acc[mt][nt][3] + b1, 0.f);
                if (row < M) {
                    *(uint32_t*)(Oh + (size_t)row * N + col) = pack_hi(v00, v01);
                    *(uint32_t*)(Ol + (size_t)row * N + col) = pack_lo(v00, v01);
                }
                if (row + 8 < M) {
                    *(uint32_t*)(Oh + (size_t)(row + 8) * N + col) = pack_hi(v10, v11);
                    *(uint32_t*)(Ol + (size_t)(row + 8) * N + col) = pack_lo(v10, v11);
                }
            }
        }
    } else {
        // register-reduce + warp-shuffle reduce; lanes 0-3 issue 4 atomics each.
#pragma unroll
        for (int nt = 0; nt < 8; nt++) {
            int col = bn + wn * 64 + nt * 8 + (lane & 3) * 2;
            float b0 = bias[col], b1 = bias[col + 1];
            float s0 = 0.f, s1 = 0.f, q0 = 0.f, q1 = 0.f;
#pragma unroll
            for (int mt = 0; mt < 2; mt++) {
                int row = bm + wm * 32 + mt * 16 + (lane >> 2);
                float v00 = acc[mt][nt][0] + b0, v01 = acc[mt][nt][1] + b1;
                float v10 = acc[mt][nt][2] + b0, v11 = acc[mt][nt][3] + b1;
                if (row < M) {
                    *(float2*)(Of + (size_t)row * N + col) = make_float2(v00, v01);
                    s0 += v00; s1 += v01;
                    q0 += v00 * v00; q1 += v01 * v01;
                }
                if (row + 8 < M) {
                    *(float2*)(Of + (size_t)(row + 8) * N + col) = make_float2(v10, v11);
                    s0 += v10; s1 += v11;
                    q0 += v10 * v10; q1 += v11 * v11;
                }
            }
#pragma unroll
            for (int delta = 16; delta >= 4; delta >>= 1) {
                s0 += __shfl_down_sync(0xffffffffu, s0, delta);
                s1 += __shfl_down_sync(0xffffffffu, s1, delta);
                q0 += __shfl_down_sync(0xffffffffu, q0, delta);
                q1 += __shfl_down_sync(0xffffffffu, q1, delta);
            }
            if (lane < 4) {
                int lc = col - bn;
                atomicAdd(&ssum[lc], s0);     atomicAdd(&ssum[lc + 1], s1);
                atomicAdd(&ssq[lc], q0);      atomicAdd(&ssq[lc + 1], q1);
            }
        }
        __syncthreads();
        if (tid < 128) {
            atomicAdd(&g_sum[tid], (double)ssum[tid]);
            atomicAdd(&g_sumsq[tid], (double)ssq[tid]);
        }
    }
}

// ---------------- seed (+ zero degree counters) ----------------
__global__ void seed_kernel(
    const int* __restrict__ an, const int* __restrict__ fc, const int* __restrict__ ct,
    const int* __restrict__ hy, const int* __restrict__ nh, const int* __restrict__ ar,
    const float* __restrict__ Ean, const float* __restrict__ Efc, const float* __restrict__ Ect,
    const float* __restrict__ Ehy, const float* __restrict__ Enh, const float* __restrict__ Ear)
{
    int gt = blockIdx.x * blockDim.x + threadIdx.x;
    if (gt < NN) g_cursor[gt] = 0;
    int w = gt >> 5;
    if (w >= NN) return;
    int d = (threadIdx.x & 31) * 4;
    float4 v = ld4(Ean + (size_t)an[w] * DD + d);
    add4(v, ld4(Efc + (size_t)fc[w] * DD + d));
    add4(v, ld4(Ect + (size_t)ct[w] * DD + d));
    add4(v, ld4(Ehy + (size_t)hy[w] * DD + d));
    add4(v, ld4(Enh + (size_t)nh[w] * DD + d));
    add4(v, ld4(Ear + (size_t)ar[w] * DD + d));
    *reinterpret_cast<float4*>(g_h + (size_t)w * DD + d) = v;
}

// ---------------- CSR build ----------------
__global__ void deg_count_kernel(const int* __restrict__ dst) {
    int e = blockIdx.x * blockDim.x + threadIdx.x;
    if (e < EE) atomicAdd(&g_cursor[dst[e]], 1);
}
__global__ void scan_chunks_kernel() {
    __shared__ int s[1024];
    int i = blockIdx.x * 1024 + threadIdx.x;
    int v = (i < NN) ? g_cursor[i] : 0;
    s[threadIdx.x] = v;
    __syncthreads();
#pragma unroll
    for (int off = 1; off < 1024; off <<= 1) {
        int x = (threadIdx.x >= off) ? s[threadIdx.x - off] : 0;
        __syncthreads();
        s[threadIdx.x] += x;
        __syncthreads();
    }
    if (i < NN) g_offs[i] = s[threadIdx.x] - v;
    if (threadIdx.x == 1023) g_chunksums[blockIdx.x] = s[1023];
}
__global__ void scan_apply_kernel() {
    __shared__ int base_s;
    if (threadIdx.x == 0) {
        int myChunk = (blockIdx.x * 256) >> 10;
        int b = 0;
        for (int i = 0; i < myChunk; i++) b += g_chunksums[i];
        base_s = b;
    }
    __syncthreads();
    int i = blockIdx.x * 256 + threadIdx.x;
    if (i < NN) {
        int o = g_offs[i] + base_s;
        g_offs[i] = o;
        g_cursor[i] = o;
    }
    if (i == 0) g_offs[NN] = EE;
}

static __device__ __forceinline__ void combo_row(
    int w, int d,
    const float* __restrict__ ec, const float* __restrict__ ea,
    const float* __restrict__ eb, const float* __restrict__ ed,
    const float* __restrict__ es, float* __restrict__ out)
{
    int c = w;
    int vbs = c % 6; c /= 6;
    int vbd = c % 7; c /= 7;
    int vbt = c % 22; c /= 22;
    int via = c & 1;
    int vic = c >> 1;
    float4 v = ld4(ec + (size_t)vic * DD + d);
    add4(v, ld4(ea + (size_t)via * DD + d));
    add4(v, ld4(eb + (size_t)vbt * DD + d));
    add4(v, ld4(ed + (size_t)vbd * DD + d));
    add4(v, ld4(es + (size_t)vbs * DD + d));
    *reinterpret_cast<float4*>(out + (size_t)w * DD + d) = v;
}

// csr_fill + layer-0 combo table, fused (disjoint block ranges)
__global__ void csr_fill_combo_kernel(
    const int* __restrict__ src, const int* __restrict__ dst,
    const int* __restrict__ ic, const int* __restrict__ ia,
    const int* __restrict__ bt, const int* __restrict__ bd,
    const int* __restrict__ bs,
    const float* __restrict__ ec, const float* __restrict__ ea,
    const float* __restrict__ eb, const float* __restrict__ ed,
    const float* __restrict__ es, int edge_blocks)
{
    if ((int)blockIdx.x < edge_blocks) {
        int e = blockIdx.x * 256 + threadIdx.x;
        if (e >= EE) return;
        int pos = atomicAdd(&g_cursor[dst[e]], 1);
        int c = (((ic[e] * 2 + ia[e]) * 22 + bt[e]) * 7 + bd[e]) * 6 + bs[e];
        g_edge_data[pos] = make_int2(src[e], c);
    } else {
        int w = ((blockIdx.x - edge_blocks) * 256 + threadIdx.x) >> 5;
        if (w >= COMBO) return;
        combo_row(w, (threadIdx.x & 31) * 4, ec, ea, eb, ed, es, g_combo);
    }
}

// ---- per-layer prep: wsplit W1 | wsplit W2 | combo (l>0); zero stats --------
__global__ void prep_kernel(
    const float* __restrict__ w1, const float* __restrict__ w2,
    const float* __restrict__ ec, const float* __restrict__ ea,
    const float* __restrict__ eb, const float* __restrict__ ed,
    const float* __restrict__ es)
{
    const int bx = blockIdx.x;
    const int tid = threadIdx.x;
    if (bx < WS_BLOCKS) {
        if (bx == 0 && tid < DD) { g_sum[tid] = 0.0; g_sumsq[tid] = 0.0; }
        int i = bx * 256 + tid;
        float x = w1[i];
        __nv_bfloat16 h = __float2bfloat16(x);
        g_w1h[i] = h;
        g_w1l[i] = __float2bfloat16(x - __bfloat162float(h));
    } else if (bx < 2 * WS_BLOCKS) {
        int i = (bx - WS_BLOCKS) * 256 + tid;
        float x = w2[i];
        __nv_bfloat16 h = __float2bfloat16(x);
        g_w2h[i] = h;
        g_w2l[i] = __float2bfloat16(x - __bfloat162float(h));
    } else {
        int w = ((bx - 2 * WS_BLOCKS) * 256 + tid) >> 5;
        if (w >= COMBO) return;
        combo_row(w, (tid & 31) * 4, ec, ea, eb, ed, es, g_combo);
    }
}

// ---------------- aggregation: gather + bf16 split output ----------------
__global__ void aggregate_kernel() {
    int w = (blockIdx.x * blockDim.x + threadIdx.x) >> 5;
    if (w >= NN) return;
    int d = (threadIdx.x & 31) * 4;
    float4 v = ld4(g_h + (size_t)w * DD + d);
    add4(v, ld4(g_combo + d));
    int beg = g_offs[w], end = g_offs[w + 1];
    for (int i = beg; i < end; i++) {
        int2 ed = g_edge_data[i];
        add4(v, ld4(g_h + (size_t)ed.x * DD + d));
        add4(v, ld4(g_combo + (size_t)ed.y * DD + d));
    }
    uint2 hi, lo;
    hi.x = pack_hi(v.x, v.y); hi.y = pack_hi(v.z, v.w);
    lo.x = pack_lo(v.x, v.y); lo.y = pack_lo(v.z, v.w);
    *(uint2*)(g_agg_h + (size_t)w * DD + d) = hi;
    *(uint2*)(g_agg_l + (size_t)w * DD + d) = lo;
}

// ---------------- batch norm ----------------
__global__ void bn_finalize_kernel(
    const float* __restrict__ gamma, const float* __restrict__ beta)
{
    int d = threadIdx.x;
    if (d < DD) {
        double m = g_sum[d] / (double)NN;
        double var = g_sumsq[d] / (double)NN - m * m;
        float sc = gamma[d] * rsqrtf((float)var + BN_EPS);
        g_scale[d] = sc;
        g_shift[d] = beta[d] - sc * (float)m;
    }
}
__global__ void bn_apply_kernel(
    const float* __restrict__ x, float* __restrict__ out, int relu)
{
    int base = blockIdx.x * blockDim.x * 2 + threadIdx.x;
    int d = (threadIdx.x & (DD / 4 - 1)) * 4;   // same column phase for both items
    float4 sc = ld4(g_scale + d);
    float4 sh = ld4(g_shift + d);
#pragma unroll
    for (int r = 0; r < 2; r++) {
        int i = base + r * blockDim.x;
        if (i >= NN * DD / 4) return;
        float4 v = ld4(x + (size_t)i * 4);
        v.x = fmaf(sc.x, v.x, sh.x);
        v.y = fmaf(sc.y, v.y, sh.y);
        v.z = fmaf(sc.z, v.z, sh.z);
        v.w = fmaf(sc.w, v.w, sh.w);
        if (relu) {
            v.x = fmaxf(v.x, 0.f); v.y = fmaxf(v.y, 0.f);
            v.z = fmaxf(v.z, 0.f); v.w = fmaxf(v.w, 0.f);
        }
        *reinterpret_cast<float4*>(out + (size_t)i * 4) = v;
    }
}

// ---------------- host launcher ----------------
extern "C" void kernel_launch(void* const* d_in, const int* in_sizes, int n_in,
                              void* d_out, int out_size)
{
    const int* atomic_num      = (const int*)d_in[0];
    const int* formal_charge   = (const int*)d_in[1];
    const int* chiral_tag      = (const int*)d_in[2];
    const int* hybridization   = (const int*)d_in[3];
    const int* num_explicit_hs = (const int*)d_in[4];
    const int* is_aromatic     = (const int*)d_in[5];
    const int* edge_index      = (const int*)d_in[6];
    const int* is_conjugated   = (const int*)d_in[7];
    const int* edge_is_arom    = (const int*)d_in[8];
    const int* bond_type       = (const int*)d_in[9];
    const int* bond_dir        = (const int*)d_in[10];
    const int* bond_stereo     = (const int*)d_in[11];
    const float* emb_atomic_num      = (const float*)d_in[12];
    const float* emb_formal_charge   = (const float*)d_in[13];
    const float* emb_chiral_tag      = (const float*)d_in[14];
    const float* emb_hybridization   = (const float*)d_in[15];
    const float* emb_num_explicit_hs = (const float*)d_in[16];
    const float* emb_is_aromatic     = (const float*)d_in[17];
    const float* e_conj    = (const float*)d_in[18];
    const float* e_arom    = (const float*)d_in[19];
    const float* e_btype   = (const float*)d_in[20];
    const float* e_bdir    = (const float*)d_in[21];
    const float* e_bstereo = (const float*)d_in[22];
    const float* mlp_w1 = (const float*)d_in[23];
    const float* mlp_b1 = (const float*)d_in[24];
    const float* mlp_w2 = (const float*)d_in[25];
    const float* mlp_b2 = (const float*)d_in[26];
    const float* bn_gamma = (const float*)d_in[27];
    const float* bn_beta  = (const float*)d_in[28];

    const int* src = edge_index;
    const int* dst = edge_index + EE;

    float* h_ptr; cudaGetSymbolAddress((void**)&h_ptr, g_h);
    __nv_bfloat16 *aggh, *aggl, *hidh, *hidl, *w1h, *w1l, *w2h, *w2l;
    cudaGetSymbolAddress((void**)&aggh, g_agg_h);
    cudaGetSymbolAddress((void**)&aggl, g_agg_l);
    cudaGetSymbolAddress((void**)&hidh, g_hid_h);
    cudaGetSymbolAddress((void**)&hidl, g_hid_l);
    cudaGetSymbolAddress((void**)&w1h, g_w1h);
    cudaGetSymbolAddress((void**)&w1l, g_w1l);
    cudaGetSymbolAddress((void**)&w2h, g_w2h);
    cudaGetSymbolAddress((void**)&w2l, g_w2l);

    cudaFuncSetAttribute(hsplit_gemm<256, 128, 0>,
                         cudaFuncAttributeMaxDynamicSharedMemorySize, GEMM_SMEM);
    cudaFuncSetAttribute(hsplit_gemm<128, 256, 1>,
                         cudaFuncAttributeMaxDynamicSharedMemorySize, GEMM_SMEM);

    const int warp_node_blocks = (NN * 32 + 255) / 256;
    const int edge_blocks = (EE + 255) / 256;
    const int node_blocks = (NN + 255) / 256;
    const int mtiles = (NN + 127) / 128;

    seed_kernel<<<warp_node_blocks, 256>>>(
        atomic_num, formal_charge, chiral_tag, hybridization,
        num_explicit_hs, is_aromatic,
        emb_atomic_num, emb_formal_charge, emb_chiral_tag,
        emb_hybridization, emb_num_explicit_hs, emb_is_aromatic);

    deg_count_kernel<<<edge_blocks, 256>>>(dst);
    scan_chunks_kernel<<<NCHUNK, 1024>>>();
    scan_apply_kernel<<<node_blocks, 256>>>();
    csr_fill_combo_kernel<<<edge_blocks + COMBO_BLOCKS, 256>>>(
        src, dst, is_conjugated, edge_is_arom, bond_type, bond_dir, bond_stereo,
        e_conj, e_arom, e_btype, e_bdir, e_bstereo, edge_blocks);

    for (int l = 0; l < LL; l++) {
        int prep_blocks = 2 * WS_BLOCKS + (l > 0 ? COMBO_BLOCKS : 0);
        prep_kernel<<<prep_blocks, 256>>>(
            mlp_w1 + (size_t)l * DD * 2 * DD,
            mlp_w2 + (size_t)l * 2 * DD * DD,
            e_conj    + (size_t)l * 3 * DD,
            e_arom    + (size_t)l * 3 * DD,
            e_btype   + (size_t)l * 23 * DD,
            e_bdir    + (size_t)l * 8 * DD,
            e_bstereo + (size_t)l * 7 * DD);

        aggregate_kernel<<<warp_node_blocks, 256>>>();

        {
            dim3 grid(2, mtiles);
            hsplit_gemm<256, 128, 0><<<grid, 256, GEMM_SMEM>>>(
                aggh, aggl, w1h, w1l,
                mlp_b1 + (size_t)l * 2 * DD, hidh, hidl, nullptr, NN);
        }
        {
            dim3 grid(1, mtiles);
            hsplit_gemm<128, 256, 1><<<grid, 256, GEMM_SMEM>>>(
                hidh, hidl, w2h, w2l,
                mlp_b2 + (size_t)l * DD, nullptr, nullptr, h_ptr, NN);
        }

        bn_finalize_kernel<<<1, 128>>>(
            bn_gamma + (size_t)l * DD, bn_beta + (size_t)l * DD);

        float* out = (l == LL - 1) ? (float*)d_out : h_ptr;
        bn_apply_kernel<<<(NN * DD / 8 + 255) / 256, 256>>>(
            h_ptr, out, (l < LL - 1) ? 1 : 0);
    }
}